// round 1
// baseline (speedup 1.0000x reference)
#include <cuda_runtime.h>
#include <math.h>

#define N_NODES 20000
#define N_EDGES 320000
#define F_LAT   128

// ---------------- scratch (static device globals; no allocation) ----------------
__device__ float g_deg[N_NODES];
__device__ float g_dis[N_NODES];
__device__ int   g_cnt[N_NODES];
__device__ int   g_cur[N_NODES];
__device__ int   g_rowptr[N_NODES + 1];
__device__ int   g_srcs[N_EDGES];
__device__ float g_vals[N_EDGES];
__device__ float g_Lx[(size_t)N_NODES * 256];
__device__ float g_Lh[(size_t)N_NODES * 256];
__device__ float g_Lhr[(size_t)N_NODES * 256];
__device__ float g_hr[(size_t)N_NODES * 256];
__device__ float g_ZR[(size_t)N_NODES * 512];
__device__ float g_Wzr[1024 * 512];
__device__ float g_WhP[1024 * 256];
__device__ float g_bzr[512];
__device__ float g_bh[256];

// ---------------- setup kernels ----------------
__global__ void zero_kernel() {
    int i = blockIdx.x * blockDim.x + threadIdx.x;
    if (i < N_NODES) { g_deg[i] = 0.f; g_cnt[i] = 0; g_cur[i] = 0; }
}

__global__ void deg_hist_kernel(const int* __restrict__ ei, const float* __restrict__ w) {
    int e = blockIdx.x * blockDim.x + threadIdx.x;
    if (e < N_EDGES) {
        int s = ei[e];
        int d = ei[N_EDGES + e];
        atomicAdd(&g_deg[s], w[e]);
        atomicAdd(&g_cnt[d], 1);
    }
}

__global__ void dis_kernel() {
    int i = blockIdx.x * blockDim.x + threadIdx.x;
    if (i < N_NODES) {
        float dg = g_deg[i];
        g_dis[i] = (dg > 0.f) ? rsqrtf(dg) : 0.f;
    }
}

// single-block exclusive scan of g_cnt -> g_rowptr
__global__ void scan_kernel() {
    __shared__ int sh[1024];
    int tid = threadIdx.x;
    if (tid == 0) g_rowptr[0] = 0;
    int carry = 0;
    for (int base = 0; base < N_NODES; base += 1024) {
        int i = base + tid;
        int v = (i < N_NODES) ? g_cnt[i] : 0;
        sh[tid] = v;
        __syncthreads();
        #pragma unroll
        for (int off = 1; off < 1024; off <<= 1) {
            int t = (tid >= off) ? sh[tid - off] : 0;
            __syncthreads();
            sh[tid] += t;
            __syncthreads();
        }
        int incl = sh[tid] + carry;
        if (i < N_NODES) g_rowptr[i + 1] = incl;
        __syncthreads();
        if (tid == 1023) sh[0] = incl;
        __syncthreads();
        carry = sh[0];
        __syncthreads();
    }
}

__global__ void scatter_kernel(const int* __restrict__ ei, const float* __restrict__ w) {
    int e = blockIdx.x * blockDim.x + threadIdx.x;
    if (e < N_EDGES) {
        int s = ei[e];
        int d = ei[N_EDGES + e];
        int pos = g_rowptr[d] + atomicAdd(&g_cur[d], 1);
        g_srcs[pos] = s;
        g_vals[pos] = -g_dis[s] * w[e] * g_dis[d];
    }
}

// pack fused weight matrices: Wzr [1024x512] (k-blocks: x,Lx,h,Lh), WhP [1024x256]
__global__ void pack_w_kernel(const float* __restrict__ Wxz, const float* __restrict__ Whz,
                              const float* __restrict__ Wxr, const float* __restrict__ Whr,
                              const float* __restrict__ Wxh, const float* __restrict__ Whh) {
    int idx = blockIdx.x * blockDim.x + threadIdx.x;
    if (idx < 1024 * 512) {
        int k = idx >> 9;       // 0..1023
        int j = idx & 511;      // 0..511
        int jj = j & 255;
        const float* Wx = (j < 256) ? Wxz : Wxr;
        const float* Wh = (j < 256) ? Whz : Whr;
        float v;
        if (k < 512) v = Wx[((k >= 256) ? 65536 : 0) + (k & 255) * 256 + jj];
        else         v = Wh[((k >= 768) ? 65536 : 0) + (k & 255) * 256 + jj];
        g_Wzr[idx] = v;
    } else {
        int i2 = idx - 1024 * 512;
        if (i2 < 1024 * 256) {
            int k = i2 >> 8;
            int jj = i2 & 255;
            float v;
            if (k < 512) v = Wxh[((k >= 256) ? 65536 : 0) + (k & 255) * 256 + jj];
            else         v = Whh[((k >= 768) ? 65536 : 0) + (k & 255) * 256 + jj];
            g_WhP[i2] = v;
        }
    }
}

__global__ void pack_b_kernel(const float* __restrict__ bxz, const float* __restrict__ bhz,
                              const float* __restrict__ bxr, const float* __restrict__ bhr,
                              const float* __restrict__ bxh, const float* __restrict__ bhh) {
    int i = threadIdx.x;  // 768 threads
    if (i < 256)      g_bzr[i] = bxz[i] + bhz[i];
    else if (i < 512) g_bzr[i] = bxr[i - 256] + bhr[i - 256];
    else              g_bh[i - 512] = bxh[i - 512] + bhh[i - 512];
}

// ---------------- SpMM (CSR gather, one block per dst row, 256 features) ----------------
__global__ void spmm_kernel(const float* __restrict__ V, float* __restrict__ O) {
    int d = blockIdx.x;
    int c = threadIdx.x;   // 0..255 (feature)
    int s0 = g_rowptr[d];
    int s1 = g_rowptr[d + 1];
    __shared__ int   ss[128];
    __shared__ float sv[128];
    float acc = 0.f;
    for (int base = s0; base < s1; base += 128) {
        int m = min(128, s1 - base);
        if (c < m) { ss[c] = g_srcs[base + c] << 8; sv[c] = g_vals[base + c]; }
        __syncthreads();
        int j = 0;
        for (; j + 4 <= m; j += 4) {
            float v0 = V[ss[j]     + c];
            float v1 = V[ss[j + 1] + c];
            float v2 = V[ss[j + 2] + c];
            float v3 = V[ss[j + 3] + c];
            acc = fmaf(sv[j], v0, acc);
            acc = fmaf(sv[j + 1], v1, acc);
            acc = fmaf(sv[j + 2], v2, acc);
            acc = fmaf(sv[j + 3], v3, acc);
        }
        for (; j < m; j++) acc = fmaf(sv[j], V[ss[j] + c], acc);
        __syncthreads();
    }
    O[(size_t)d * 256 + c] = acc;
}

// ---------------- elementwise: hr = h * R ----------------
__global__ void hr_kernel(const float* __restrict__ h) {
    int i = blockIdx.x * blockDim.x + threadIdx.x;
    if (i < N_NODES * 256) {
        int r = i >> 8, c = i & 255;
        g_hr[i] = h[i] * g_ZR[(size_t)r * 512 + 256 + c];
    }
}

// ---------------- SGEMM: C[M,Nc] = concat_A[M,K] @ B[K,Nc] (+epilogue) ----------------
// A given as up to 4 row-major [M,256] sources stacked along K. BM=128 BN=64 BK=16.
// MODE 0: sigmoid -> C (ldc=Nc).  MODE 1: GRU combine -> C (ldc=256).  MODE 2: bias -> C.
template <int MODE, bool RELU_A>
__global__ void __launch_bounds__(256) gemm_kernel(
    const float* __restrict__ a0, const float* __restrict__ a1,
    const float* __restrict__ a2, const float* __restrict__ a3,
    const float* __restrict__ B,  const float* __restrict__ bias,
    float* __restrict__ C,
    const float* __restrict__ zr, const float* __restrict__ hmat,
    int M, int K, int Nc)
{
    __shared__ float As[16][136];
    __shared__ float Bs[16][64];
    const float* aptr[4] = {a0, a1, a2, a3};
    int tid = threadIdx.x;
    int tx = tid & 15;        // col group (4 cols)
    int ty = tid >> 4;        // row group (8 rows)
    int bx = blockIdx.x, by = blockIdx.y;
    int row0 = by * 128;

    float acc[8][4];
    #pragma unroll
    for (int i = 0; i < 8; i++)
        #pragma unroll
        for (int j = 0; j < 4; j++) acc[i][j] = 0.f;

    int nkt = K >> 4;
    for (int kt = 0; kt < nkt; kt++) {
        const float* A = aptr[kt >> 4];
        int kbase = (kt << 4) & 255;
        #pragma unroll
        for (int t = 0; t < 2; t++) {
            int idx4 = tid + t * 256;     // 0..511
            int r  = idx4 >> 2;           // 0..127
            int kq = idx4 & 3;            // 0..3
            int gr = row0 + r;
            float4 v = make_float4(0.f, 0.f, 0.f, 0.f);
            if (gr < M) v = *(const float4*)(A + (size_t)gr * 256 + kbase + kq * 4);
            if (RELU_A) {
                v.x = fmaxf(v.x, 0.f); v.y = fmaxf(v.y, 0.f);
                v.z = fmaxf(v.z, 0.f); v.w = fmaxf(v.w, 0.f);
            }
            As[kq * 4 + 0][r] = v.x;
            As[kq * 4 + 1][r] = v.y;
            As[kq * 4 + 2][r] = v.z;
            As[kq * 4 + 3][r] = v.w;
        }
        {
            int kk = tid >> 4;
            int c4 = tid & 15;
            float4 v = *(const float4*)(B + (size_t)(kt * 16 + kk) * Nc + bx * 64 + c4 * 4);
            *(float4*)&Bs[kk][c4 * 4] = v;
        }
        __syncthreads();
        #pragma unroll
        for (int kk = 0; kk < 16; kk++) {
            float a[8], b[4];
            #pragma unroll
            for (int i = 0; i < 8; i++) a[i] = As[kk][ty * 8 + i];
            #pragma unroll
            for (int j = 0; j < 4; j++) b[j] = Bs[kk][tx * 4 + j];
            #pragma unroll
            for (int i = 0; i < 8; i++)
                #pragma unroll
                for (int j = 0; j < 4; j++)
                    acc[i][j] = fmaf(a[i], b[j], acc[i][j]);
        }
        __syncthreads();
    }

    #pragma unroll
    for (int i = 0; i < 8; i++) {
        int gr = row0 + ty * 8 + i;
        if (gr >= M) continue;
        #pragma unroll
        for (int j = 0; j < 4; j++) {
            int gc = bx * 64 + tx * 4 + j;
            float v = acc[i][j] + bias[gc];
            if (MODE == 0) {
                v = 1.f / (1.f + expf(-v));
                C[(size_t)gr * Nc + gc] = v;
            } else if (MODE == 1) {
                float t  = tanhf(v);
                float z  = zr[(size_t)gr * 512 + gc];
                float hv = hmat[(size_t)gr * 256 + gc];
                C[(size_t)gr * 256 + gc] = z * hv + (1.f - z) * t;
            } else {
                C[(size_t)gr * Nc + gc] = v;
            }
        }
    }
}

// ---------------- launch ----------------
extern "C" void kernel_launch(void* const* d_in, const int* in_sizes, int n_in,
                              void* d_out, int out_size) {
    const float* x   = (const float*)d_in[0];
    const float* h   = (const float*)d_in[1];
    const int*   ei  = (const int*)d_in[2];
    const float* w   = (const float*)d_in[3];
    const float* Wxz = (const float*)d_in[4];  const float* bxz = (const float*)d_in[5];
    const float* Whz = (const float*)d_in[6];  const float* bhz = (const float*)d_in[7];
    const float* Wxr = (const float*)d_in[8];  const float* bxr = (const float*)d_in[9];
    const float* Whr = (const float*)d_in[10]; const float* bhr = (const float*)d_in[11];
    const float* Wxh = (const float*)d_in[12]; const float* bxh = (const float*)d_in[13];
    const float* Whh = (const float*)d_in[14]; const float* bhh = (const float*)d_in[15];
    const float* Wl  = (const float*)d_in[16]; const float* bl  = (const float*)d_in[17];

    float* out = (float*)d_out;                       // [N,128]
    float* h0  = out + (size_t)N_NODES * F_LAT;       // [N,256]

    // symbol addresses for passing scratch as kernel args
    float *p_Lx, *p_Lh, *p_Lhr, *p_hr, *p_ZR, *p_Wzr, *p_WhP, *p_bzr, *p_bh;
    cudaGetSymbolAddress((void**)&p_Lx,  g_Lx);
    cudaGetSymbolAddress((void**)&p_Lh,  g_Lh);
    cudaGetSymbolAddress((void**)&p_Lhr, g_Lhr);
    cudaGetSymbolAddress((void**)&p_hr,  g_hr);
    cudaGetSymbolAddress((void**)&p_ZR,  g_ZR);
    cudaGetSymbolAddress((void**)&p_Wzr, g_Wzr);
    cudaGetSymbolAddress((void**)&p_WhP, g_WhP);
    cudaGetSymbolAddress((void**)&p_bzr, g_bzr);
    cudaGetSymbolAddress((void**)&p_bh,  g_bh);

    // graph normalization + CSR build
    zero_kernel<<<(N_NODES + 255) / 256, 256>>>();
    deg_hist_kernel<<<(N_EDGES + 255) / 256, 256>>>(ei, w);
    dis_kernel<<<(N_NODES + 255) / 256, 256>>>();
    scan_kernel<<<1, 1024>>>();
    scatter_kernel<<<(N_EDGES + 255) / 256, 256>>>(ei, w);

    // pack fused weights / biases (cheap; deterministic every call)
    pack_w_kernel<<<(1024 * 512 + 1024 * 256 + 255) / 256, 256>>>(Wxz, Whz, Wxr, Whr, Wxh, Whh);
    pack_b_kernel<<<1, 768>>>(bxz, bhz, bxr, bhr, bxh, bhh);

    // SpMMs: Lx, Lh
    spmm_kernel<<<N_NODES, 256>>>(x, p_Lx);
    spmm_kernel<<<N_NODES, 256>>>(h, p_Lh);

    // ZR = sigmoid([x|Lx|h|Lh] @ Wzr + bzr)   -> g_ZR [N,512]
    {
        dim3 grid(512 / 64, (N_NODES + 127) / 128);
        gemm_kernel<0, false><<<grid, 256>>>(x, p_Lx, h, p_Lh, p_Wzr, p_bzr, p_ZR,
                                             nullptr, nullptr, N_NODES, 1024, 512);
    }

    // hr = h * R ; L(hr)
    hr_kernel<<<(N_NODES * 256 + 255) / 256, 256>>>(h);
    spmm_kernel<<<N_NODES, 256>>>(p_hr, p_Lhr);

    // h0 = Z*h + (1-Z)*tanh([x|Lx|hr|Lhr] @ WhP + bh)  -> d_out h0 region
    {
        dim3 grid(256 / 64, (N_NODES + 127) / 128);
        gemm_kernel<1, false><<<grid, 256>>>(x, p_Lx, p_hr, p_Lhr, p_WhP, p_bh, h0,
                                             p_ZR, h, N_NODES, 1024, 256);
    }

    // out = relu(h0) @ Wl + bl  -> d_out [N,128]
    {
        dim3 grid(128 / 64, (N_NODES + 127) / 128);
        gemm_kernel<2, true><<<grid, 256>>>(h0, h0, h0, h0, Wl, bl, out,
                                            nullptr, nullptr, N_NODES, 256, 128);
    }
}

// round 2
// speedup vs baseline: 1.7638x; 1.7638x over previous
#include <cuda_runtime.h>
#include <math.h>

#define N_NODES 20000
#define N_EDGES 320000
#define F_LAT   128

// ---------------- scratch (static device globals; no allocation) ----------------
__device__ float g_deg[N_NODES];
__device__ float g_dis[N_NODES];
__device__ int   g_cnt[N_NODES];
__device__ int   g_cur[N_NODES];
__device__ int   g_rowptr[N_NODES + 1];
__device__ int   g_srcs[N_EDGES];
__device__ float g_vals[N_EDGES];
__device__ float g_Lx[(size_t)N_NODES * 256];
__device__ float g_Lh[(size_t)N_NODES * 256];
__device__ float g_Lhr[(size_t)N_NODES * 256];
__device__ float g_hr[(size_t)N_NODES * 256];
__device__ float g_ZR[(size_t)N_NODES * 512];
__device__ float g_Wzr[1024 * 512];
__device__ float g_WhP[1024 * 256];
__device__ float g_bzr[512];
__device__ float g_bh[256];

// ---------------- setup kernels ----------------
__global__ void zero_kernel() {
    int i = blockIdx.x * blockDim.x + threadIdx.x;
    if (i < N_NODES) { g_deg[i] = 0.f; g_cnt[i] = 0; g_cur[i] = 0; }
}

__global__ void deg_hist_kernel(const int* __restrict__ ei, const float* __restrict__ w) {
    int e = blockIdx.x * blockDim.x + threadIdx.x;
    if (e < N_EDGES) {
        int s = ei[e];
        int d = ei[N_EDGES + e];
        atomicAdd(&g_deg[s], w[e]);
        atomicAdd(&g_cnt[d], 1);
    }
}

__global__ void dis_kernel() {
    int i = blockIdx.x * blockDim.x + threadIdx.x;
    if (i < N_NODES) {
        float dg = g_deg[i];
        g_dis[i] = (dg > 0.f) ? rsqrtf(dg) : 0.f;
    }
}

// fast single-block scan: each thread owns 20 elements, shuffle-scan the totals
__global__ void scan_kernel() {
    __shared__ int warp_sums[32];
    const int PER = 20;  // 1024 * 20 >= 20000
    int tid = threadIdx.x;
    int base = tid * PER;
    int loc[PER];
    int s = 0;
    #pragma unroll
    for (int i = 0; i < PER; i++) {
        int idx = base + i;
        int v = (idx < N_NODES) ? g_cnt[idx] : 0;
        loc[i] = s;
        s += v;
    }
    int lane = tid & 31, wid = tid >> 5;
    int v = s;
    #pragma unroll
    for (int o = 1; o < 32; o <<= 1) {
        int t = __shfl_up_sync(0xFFFFFFFFu, v, o);
        if (lane >= o) v += t;
    }
    if (lane == 31) warp_sums[wid] = v;
    __syncthreads();
    if (wid == 0) {
        int wv = warp_sums[lane];
        #pragma unroll
        for (int o = 1; o < 32; o <<= 1) {
            int t = __shfl_up_sync(0xFFFFFFFFu, wv, o);
            if (lane >= o) wv += t;
        }
        warp_sums[lane] = wv;
    }
    __syncthreads();
    int ex = v - s + (wid ? warp_sums[wid - 1] : 0);  // exclusive prefix for this thread's chunk
    #pragma unroll
    for (int i = 0; i < PER; i++) {
        int idx = base + i;
        if (idx < N_NODES) g_rowptr[idx] = ex + loc[i];
    }
    if (tid == 1023) g_rowptr[N_NODES] = ex + s;
}

__global__ void scatter_kernel(const int* __restrict__ ei, const float* __restrict__ w) {
    int e = blockIdx.x * blockDim.x + threadIdx.x;
    if (e < N_EDGES) {
        int s = ei[e];
        int d = ei[N_EDGES + e];
        int pos = g_rowptr[d] + atomicAdd(&g_cur[d], 1);
        g_srcs[pos] = s;
        g_vals[pos] = -g_dis[s] * w[e] * g_dis[d];
    }
}

// pack fused weight matrices: Wzr [1024x512] (k-blocks: x,Lx,h,Lh), WhP [1024x256]
__global__ void pack_w_kernel(const float* __restrict__ Wxz, const float* __restrict__ Whz,
                              const float* __restrict__ Wxr, const float* __restrict__ Whr,
                              const float* __restrict__ Wxh, const float* __restrict__ Whh) {
    int idx = blockIdx.x * blockDim.x + threadIdx.x;
    if (idx < 1024 * 512) {
        int k = idx >> 9;       // 0..1023
        int j = idx & 511;      // 0..511
        int jj = j & 255;
        const float* Wx = (j < 256) ? Wxz : Wxr;
        const float* Wh = (j < 256) ? Whz : Whr;
        float v;
        if (k < 512) v = Wx[((k >= 256) ? 65536 : 0) + (k & 255) * 256 + jj];
        else         v = Wh[((k >= 768) ? 65536 : 0) + (k & 255) * 256 + jj];
        g_Wzr[idx] = v;
    } else {
        int i2 = idx - 1024 * 512;
        if (i2 < 1024 * 256) {
            int k = i2 >> 8;
            int jj = i2 & 255;
            float v;
            if (k < 512) v = Wxh[((k >= 256) ? 65536 : 0) + (k & 255) * 256 + jj];
            else         v = Whh[((k >= 768) ? 65536 : 0) + (k & 255) * 256 + jj];
            g_WhP[i2] = v;
        }
    }
}

__global__ void pack_b_kernel(const float* __restrict__ bxz, const float* __restrict__ bhz,
                              const float* __restrict__ bxr, const float* __restrict__ bhr,
                              const float* __restrict__ bxh, const float* __restrict__ bhh) {
    int i = threadIdx.x;  // 768 threads
    if (i < 256)      g_bzr[i] = bxz[i] + bhz[i];
    else if (i < 512) g_bzr[i] = bxr[i - 256] + bhr[i - 256];
    else              g_bh[i - 512] = bxh[i - 512] + bhh[i - 512];
}

// ---------------- SpMM (CSR gather, one block per dst row, 256 features) ----------------
__global__ void spmm_kernel(const float* __restrict__ V, float* __restrict__ O) {
    int d = blockIdx.x;
    int c = threadIdx.x;   // 0..255 (feature)
    int s0 = g_rowptr[d];
    int s1 = g_rowptr[d + 1];
    __shared__ int   ss[128];
    __shared__ float sv[128];
    float acc = 0.f;
    for (int base = s0; base < s1; base += 128) {
        int m = min(128, s1 - base);
        if (c < m) { ss[c] = g_srcs[base + c] << 8; sv[c] = g_vals[base + c]; }
        __syncthreads();
        int j = 0;
        for (; j + 4 <= m; j += 4) {
            float v0 = V[ss[j]     + c];
            float v1 = V[ss[j + 1] + c];
            float v2 = V[ss[j + 2] + c];
            float v3 = V[ss[j + 3] + c];
            acc = fmaf(sv[j], v0, acc);
            acc = fmaf(sv[j + 1], v1, acc);
            acc = fmaf(sv[j + 2], v2, acc);
            acc = fmaf(sv[j + 3], v3, acc);
        }
        for (; j < m; j++) acc = fmaf(sv[j], V[ss[j] + c], acc);
        __syncthreads();
    }
    O[(size_t)d * 256 + c] = acc;
}

// ---------------- elementwise: hr = h * R ----------------
__global__ void hr_kernel(const float* __restrict__ h) {
    int i = blockIdx.x * blockDim.x + threadIdx.x;
    if (i < N_NODES * 256) {
        int r = i >> 8, c = i & 255;
        g_hr[i] = h[i] * g_ZR[(size_t)r * 512 + 256 + c];
    }
}

// ---------------- TF32 tensor-core GEMM ----------------
__device__ __forceinline__ unsigned f2tf(float f) {
    unsigned r;
    asm("cvt.rna.tf32.f32 %0, %1;" : "=r"(r) : "f"(f));
    return r;
}

__device__ __forceinline__ void mma_tf32(float c[4], const unsigned a[4], const unsigned b[2]) {
    asm volatile(
        "mma.sync.aligned.m16n8k8.row.col.f32.tf32.tf32.f32 "
        "{%0,%1,%2,%3},{%4,%5,%6,%7},{%8,%9},{%0,%1,%2,%3};"
        : "+f"(c[0]), "+f"(c[1]), "+f"(c[2]), "+f"(c[3])
        : "r"(a[0]), "r"(a[1]), "r"(a[2]), "r"(a[3]), "r"(b[0]), "r"(b[1]));
}

// C[M,Nc] = concat_A[M,K] @ B[K,Nc] (+epilogue). A = up to 4 row-major [M,256] slabs along K.
// BM=128 BN=64 BK=16. 8 warps in 4x2 grid, warp tile 32x32 via m16n8k8 tf32.
// MODE 0: sigmoid (ldc=Nc). MODE 1: GRU combine (ldc=256). MODE 2: bias only.
template <int MODE, bool RELU_A>
__global__ void __launch_bounds__(256) gemm_tc(
    const float* __restrict__ a0, const float* __restrict__ a1,
    const float* __restrict__ a2, const float* __restrict__ a3,
    const float* __restrict__ B,  const float* __restrict__ bias,
    float* __restrict__ C,
    const float* __restrict__ zr, const float* __restrict__ hmat,
    int M, int K, int Nc)
{
    __shared__ unsigned As[16][136];   // [k][m], stride%32==8 -> conflict-free frag loads
    __shared__ unsigned Bs[16][72];    // [k][n]
    const float* aptr[4] = {a0, a1, a2, a3};
    int tid = threadIdx.x;
    int w = tid >> 5, lane = tid & 31;
    int wr = w >> 1, wc = w & 1;         // warp grid 4x2
    int gid = lane >> 2, tig = lane & 3;
    int bx = blockIdx.x, by = blockIdx.y;
    int row0 = by * 128;

    float c[2][4][4];
    #pragma unroll
    for (int mt = 0; mt < 2; mt++)
        #pragma unroll
        for (int nt = 0; nt < 4; nt++)
            #pragma unroll
            for (int i = 0; i < 4; i++) c[mt][nt][i] = 0.f;

    // staging regs for double buffering
    float4 Ara0, Ara1, Brb;
    int ar = tid >> 1;                 // A row 0..127
    int akq = (tid & 1) * 8;           // A col offset 0 or 8
    int bkk = tid >> 4;                // B k row 0..15
    int bc4 = tid & 15;                // B col group

    auto load_regs = [&](int kt) {
        const float* A = aptr[kt >> 4];
        int kbase = (kt & 15) * 16;
        int gr = row0 + ar;
        if (gr < M) {
            Ara0 = *(const float4*)(A + (size_t)gr * 256 + kbase + akq);
            Ara1 = *(const float4*)(A + (size_t)gr * 256 + kbase + akq + 4);
        } else {
            Ara0 = make_float4(0.f, 0.f, 0.f, 0.f);
            Ara1 = Ara0;
        }
        if (RELU_A) {
            Ara0.x = fmaxf(Ara0.x, 0.f); Ara0.y = fmaxf(Ara0.y, 0.f);
            Ara0.z = fmaxf(Ara0.z, 0.f); Ara0.w = fmaxf(Ara0.w, 0.f);
            Ara1.x = fmaxf(Ara1.x, 0.f); Ara1.y = fmaxf(Ara1.y, 0.f);
            Ara1.z = fmaxf(Ara1.z, 0.f); Ara1.w = fmaxf(Ara1.w, 0.f);
        }
        Brb = *(const float4*)(B + (size_t)(kt * 16 + bkk) * Nc + bx * 64 + bc4 * 4);
    };
    auto store_smem = [&]() {
        As[akq + 0][ar] = f2tf(Ara0.x);
        As[akq + 1][ar] = f2tf(Ara0.y);
        As[akq + 2][ar] = f2tf(Ara0.z);
        As[akq + 3][ar] = f2tf(Ara0.w);
        As[akq + 4][ar] = f2tf(Ara1.x);
        As[akq + 5][ar] = f2tf(Ara1.y);
        As[akq + 6][ar] = f2tf(Ara1.z);
        As[akq + 7][ar] = f2tf(Ara1.w);
        Bs[bkk][bc4 * 4 + 0] = f2tf(Brb.x);
        Bs[bkk][bc4 * 4 + 1] = f2tf(Brb.y);
        Bs[bkk][bc4 * 4 + 2] = f2tf(Brb.z);
        Bs[bkk][bc4 * 4 + 3] = f2tf(Brb.w);
    };

    int nkt = K >> 4;
    load_regs(0);
    store_smem();
    __syncthreads();

    for (int kt = 0; kt < nkt; kt++) {
        if (kt + 1 < nkt) load_regs(kt + 1);
        #pragma unroll
        for (int ks = 0; ks < 16; ks += 8) {
            unsigned a[2][4], b[4][2];
            #pragma unroll
            for (int mt = 0; mt < 2; mt++) {
                int m = wr * 32 + mt * 16 + gid;
                a[mt][0] = As[ks + tig][m];
                a[mt][1] = As[ks + tig][m + 8];
                a[mt][2] = As[ks + tig + 4][m];
                a[mt][3] = As[ks + tig + 4][m + 8];
            }
            #pragma unroll
            for (int nt = 0; nt < 4; nt++) {
                int n = wc * 32 + nt * 8 + gid;
                b[nt][0] = Bs[ks + tig][n];
                b[nt][1] = Bs[ks + tig + 4][n];
            }
            #pragma unroll
            for (int mt = 0; mt < 2; mt++)
                #pragma unroll
                for (int nt = 0; nt < 4; nt++)
                    mma_tf32(c[mt][nt], a[mt], b[nt]);
        }
        __syncthreads();
        if (kt + 1 < nkt) {
            store_smem();
            __syncthreads();
        }
    }

    // epilogue: c regs -> (row=gid/+8, col=2*tig/+1) per 16x8 tile; write float2
    #pragma unroll
    for (int mt = 0; mt < 2; mt++) {
        #pragma unroll
        for (int half = 0; half < 2; half++) {
            int gr = row0 + wr * 32 + mt * 16 + gid + half * 8;
            if (gr >= M) continue;
            #pragma unroll
            for (int nt = 0; nt < 4; nt++) {
                int gc = bx * 64 + wc * 32 + nt * 8 + 2 * tig;
                float v0 = c[mt][nt][half * 2 + 0] + bias[gc];
                float v1 = c[mt][nt][half * 2 + 1] + bias[gc + 1];
                if (MODE == 0) {
                    v0 = 1.f / (1.f + expf(-v0));
                    v1 = 1.f / (1.f + expf(-v1));
                    *(float2*)(C + (size_t)gr * Nc + gc) = make_float2(v0, v1);
                } else if (MODE == 1) {
                    float t0 = tanhf(v0), t1 = tanhf(v1);
                    float z0 = zr[(size_t)gr * 512 + gc];
                    float z1 = zr[(size_t)gr * 512 + gc + 1];
                    float h0v = hmat[(size_t)gr * 256 + gc];
                    float h1v = hmat[(size_t)gr * 256 + gc + 1];
                    *(float2*)(C + (size_t)gr * 256 + gc) =
                        make_float2(z0 * h0v + (1.f - z0) * t0,
                                    z1 * h1v + (1.f - z1) * t1);
                } else {
                    *(float2*)(C + (size_t)gr * Nc + gc) = make_float2(v0, v1);
                }
            }
        }
    }
}

// ---------------- launch ----------------
extern "C" void kernel_launch(void* const* d_in, const int* in_sizes, int n_in,
                              void* d_out, int out_size) {
    const float* x   = (const float*)d_in[0];
    const float* h   = (const float*)d_in[1];
    const int*   ei  = (const int*)d_in[2];
    const float* w   = (const float*)d_in[3];
    const float* Wxz = (const float*)d_in[4];  const float* bxz = (const float*)d_in[5];
    const float* Whz = (const float*)d_in[6];  const float* bhz = (const float*)d_in[7];
    const float* Wxr = (const float*)d_in[8];  const float* bxr = (const float*)d_in[9];
    const float* Whr = (const float*)d_in[10]; const float* bhr = (const float*)d_in[11];
    const float* Wxh = (const float*)d_in[12]; const float* bxh = (const float*)d_in[13];
    const float* Whh = (const float*)d_in[14]; const float* bhh = (const float*)d_in[15];
    const float* Wl  = (const float*)d_in[16]; const float* bl  = (const float*)d_in[17];

    float* out = (float*)d_out;                       // [N,128]
    float* h0  = out + (size_t)N_NODES * F_LAT;       // [N,256]

    float *p_Lx, *p_Lh, *p_Lhr, *p_hr, *p_ZR, *p_Wzr, *p_WhP, *p_bzr, *p_bh;
    cudaGetSymbolAddress((void**)&p_Lx,  g_Lx);
    cudaGetSymbolAddress((void**)&p_Lh,  g_Lh);
    cudaGetSymbolAddress((void**)&p_Lhr, g_Lhr);
    cudaGetSymbolAddress((void**)&p_hr,  g_hr);
    cudaGetSymbolAddress((void**)&p_ZR,  g_ZR);
    cudaGetSymbolAddress((void**)&p_Wzr, g_Wzr);
    cudaGetSymbolAddress((void**)&p_WhP, g_WhP);
    cudaGetSymbolAddress((void**)&p_bzr, g_bzr);
    cudaGetSymbolAddress((void**)&p_bh,  g_bh);

    // graph normalization + CSR build
    zero_kernel<<<(N_NODES + 255) / 256, 256>>>();
    deg_hist_kernel<<<(N_EDGES + 255) / 256, 256>>>(ei, w);
    dis_kernel<<<(N_NODES + 255) / 256, 256>>>();
    scan_kernel<<<1, 1024>>>();
    scatter_kernel<<<(N_EDGES + 255) / 256, 256>>>(ei, w);

    // pack fused weights / biases
    pack_w_kernel<<<(1024 * 512 + 1024 * 256 + 255) / 256, 256>>>(Wxz, Whz, Wxr, Whr, Wxh, Whh);
    pack_b_kernel<<<1, 768>>>(bxz, bhz, bxr, bhr, bxh, bhh);

    // SpMMs: Lx, Lh
    spmm_kernel<<<N_NODES, 256>>>(x, p_Lx);
    spmm_kernel<<<N_NODES, 256>>>(h, p_Lh);

    // ZR = sigmoid([x|Lx|h|Lh] @ Wzr + bzr) -> g_ZR [N,512]
    {
        dim3 grid(512 / 64, (N_NODES + 127) / 128);
        gemm_tc<0, false><<<grid, 256>>>(x, p_Lx, h, p_Lh, p_Wzr, p_bzr, p_ZR,
                                         nullptr, nullptr, N_NODES, 1024, 512);
    }

    // hr = h * R ; L(hr)
    hr_kernel<<<(N_NODES * 256 + 255) / 256, 256>>>(h);
    spmm_kernel<<<N_NODES, 256>>>(p_hr, p_Lhr);

    // h0 = Z*h + (1-Z)*tanh([x|Lx|hr|Lhr] @ WhP + bh) -> d_out h0 region
    {
        dim3 grid(256 / 64, (N_NODES + 127) / 128);
        gemm_tc<1, false><<<grid, 256>>>(x, p_Lx, p_hr, p_Lhr, p_WhP, p_bh, h0,
                                         p_ZR, h, N_NODES, 1024, 256);
    }

    // out = relu(h0) @ Wl + bl -> d_out [N,128]
    {
        dim3 grid(128 / 64, (N_NODES + 127) / 128);
        gemm_tc<2, true><<<grid, 256>>>(h0, h0, h0, h0, Wl, bl, out,
                                        nullptr, nullptr, N_NODES, 256, 128);
    }
}

// round 4
// speedup vs baseline: 2.7507x; 1.5596x over previous
#include <cuda_runtime.h>
#include <cuda_fp16.h>
#include <math.h>
#include <stdint.h>

#define N_NODES 20000
#define N_EDGES 320000

// ---------------- PTX helpers ----------------
__device__ __forceinline__ uint32_t smem_u32(const void* p) {
    uint32_t a;
    asm("{ .reg .u64 t; cvta.to.shared.u64 t, %1; cvt.u32.u64 %0, t; }" : "=r"(a) : "l"(p));
    return a;
}

__device__ __forceinline__ void ldm_x4(uint32_t r[4], uint32_t addr) {
    asm volatile("ldmatrix.sync.aligned.m8n8.x4.shared.b16 {%0,%1,%2,%3}, [%4];"
        : "=r"(r[0]), "=r"(r[1]), "=r"(r[2]), "=r"(r[3]) : "r"(addr));
}
__device__ __forceinline__ void ldm_x4_t(uint32_t r[4], uint32_t addr) {
    asm volatile("ldmatrix.sync.aligned.m8n8.x4.trans.shared.b16 {%0,%1,%2,%3}, [%4];"
        : "=r"(r[0]), "=r"(r[1]), "=r"(r[2]), "=r"(r[3]) : "r"(addr));
}
__device__ __forceinline__ void mma_f16(float* c, const uint32_t a[4], uint32_t b0, uint32_t b1) {
    asm volatile(
        "mma.sync.aligned.m16n8k16.row.col.f32.f16.f16.f32 "
        "{%0,%1,%2,%3},{%4,%5,%6,%7},{%8,%9},{%0,%1,%2,%3};"
        : "+f"(c[0]), "+f"(c[1]), "+f"(c[2]), "+f"(c[3])
        : "r"(a[0]), "r"(a[1]), "r"(a[2]), "r"(a[3]), "r"(b0), "r"(b1));
}

#define CP_COMMIT() asm volatile("cp.async.commit_group;" ::: "memory")

// ---------------- scratch (static device globals; no allocation) ----------------
__device__ float g_deg[N_NODES];
__device__ float g_dis[N_NODES];
__device__ int   g_cnt[N_NODES];
__device__ int   g_cur[N_NODES];
__device__ int   g_rowptr[N_NODES + 1];
__device__ int   g_srcs[N_EDGES];
__device__ float g_vals[N_EDGES];

__device__ __align__(16) __half g_xh  [(size_t)N_NODES * 256];
__device__ __align__(16) __half g_hh  [(size_t)N_NODES * 256];
__device__ __align__(16) __half g_Lxh [(size_t)N_NODES * 256];
__device__ __align__(16) __half g_Lhh [(size_t)N_NODES * 256];
__device__ __align__(16) __half g_hrh [(size_t)N_NODES * 256];
__device__ __align__(16) __half g_Lhrh[(size_t)N_NODES * 256];
__device__ __align__(16) __half g_h0rh[(size_t)N_NODES * 256];
__device__ float g_Z[(size_t)N_NODES * 256];

__device__ __align__(16) __half g_Wzrh[1024 * 512];   // [K=1024][N=512]
__device__ __align__(16) __half g_WhPh[1024 * 256];   // [K=1024][N=256]
__device__ __align__(16) __half g_Wlth[256 * 128];    // [K=256][N=128]
__device__ float g_bzr[512];
__device__ float g_bh[256];

// ---------------- setup kernels ----------------
__global__ void zero_kernel() {
    int i = blockIdx.x * blockDim.x + threadIdx.x;
    if (i < N_NODES) { g_deg[i] = 0.f; g_cnt[i] = 0; g_cur[i] = 0; }
}

__global__ void deg_hist_kernel(const int* __restrict__ ei, const float* __restrict__ w) {
    int e = blockIdx.x * blockDim.x + threadIdx.x;
    if (e < N_EDGES) {
        atomicAdd(&g_deg[ei[e]], w[e]);
        atomicAdd(&g_cnt[ei[N_EDGES + e]], 1);
    }
}

__global__ void dis_kernel() {
    int i = blockIdx.x * blockDim.x + threadIdx.x;
    if (i < N_NODES) {
        float dg = g_deg[i];
        g_dis[i] = (dg > 0.f) ? rsqrtf(dg) : 0.f;
    }
}

__global__ void scan_kernel() {
    __shared__ int warp_sums[32];
    const int PER = 20;
    int tid = threadIdx.x;
    int base = tid * PER;
    int loc[PER];
    int s = 0;
    #pragma unroll
    for (int i = 0; i < PER; i++) {
        int idx = base + i;
        int v = (idx < N_NODES) ? g_cnt[idx] : 0;
        loc[i] = s; s += v;
    }
    int lane = tid & 31, wid = tid >> 5;
    int v = s;
    #pragma unroll
    for (int o = 1; o < 32; o <<= 1) {
        int t = __shfl_up_sync(0xFFFFFFFFu, v, o);
        if (lane >= o) v += t;
    }
    if (lane == 31) warp_sums[wid] = v;
    __syncthreads();
    if (wid == 0) {
        int wv = warp_sums[lane];
        #pragma unroll
        for (int o = 1; o < 32; o <<= 1) {
            int t = __shfl_up_sync(0xFFFFFFFFu, wv, o);
            if (lane >= o) wv += t;
        }
        warp_sums[lane] = wv;
    }
    __syncthreads();
    int ex = v - s + (wid ? warp_sums[wid - 1] : 0);
    #pragma unroll
    for (int i = 0; i < PER; i++) {
        int idx = base + i;
        if (idx < N_NODES) g_rowptr[idx] = ex + loc[i];
    }
    if (tid == 1023) g_rowptr[N_NODES] = ex + s;
}

__global__ void scatter_kernel(const int* __restrict__ ei, const float* __restrict__ w) {
    int e = blockIdx.x * blockDim.x + threadIdx.x;
    if (e < N_EDGES) {
        int s = ei[e];
        int d = ei[N_EDGES + e];
        int pos = g_rowptr[d] + atomicAdd(&g_cur[d], 1);
        g_srcs[pos] = s;
        g_vals[pos] = -g_dis[s] * w[e] * g_dis[d];
    }
}

// convert x, h to fp16
__global__ void cvt_kernel(const float* __restrict__ x, const float* __restrict__ h) {
    int i = blockIdx.x * blockDim.x + threadIdx.x;
    if (i < N_NODES * 256) {
        g_xh[i] = __float2half_rn(x[i]);
        g_hh[i] = __float2half_rn(h[i]);
    }
}

// pack fused weights as half, [K][N] layout
__global__ void pack_w_kernel(const float* __restrict__ Wxz, const float* __restrict__ Whz,
                              const float* __restrict__ Wxr, const float* __restrict__ Whr,
                              const float* __restrict__ Wxh, const float* __restrict__ Whh,
                              const float* __restrict__ Wl) {
    int idx = blockIdx.x * blockDim.x + threadIdx.x;
    if (idx < 1024 * 512) {
        int k = idx >> 9, j = idx & 511;
        int jj = j & 255;
        const float* Wx = (j < 256) ? Wxz : Wxr;
        const float* Wh = (j < 256) ? Whz : Whr;
        float v;
        if (k < 512) v = Wx[((k >= 256) ? 65536 : 0) + (k & 255) * 256 + jj];
        else         v = Wh[((k >= 768) ? 65536 : 0) + (k & 255) * 256 + jj];
        g_Wzrh[idx] = __float2half_rn(v);
    } else if (idx < 1024 * 512 + 1024 * 256) {
        int i2 = idx - 1024 * 512;
        int k = i2 >> 8, jj = i2 & 255;
        float v;
        if (k < 512) v = Wxh[((k >= 256) ? 65536 : 0) + (k & 255) * 256 + jj];
        else         v = Whh[((k >= 768) ? 65536 : 0) + (k & 255) * 256 + jj];
        g_WhPh[i2] = __float2half_rn(v);
    } else if (idx < 1024 * 512 + 1024 * 256 + 256 * 128) {
        int i3 = idx - (1024 * 512 + 1024 * 256);
        g_Wlth[i3] = __float2half_rn(Wl[i3]);   // Wl already [K=256][N=128]
    }
}

__global__ void pack_b_kernel(const float* __restrict__ bxz, const float* __restrict__ bhz,
                              const float* __restrict__ bxr, const float* __restrict__ bhr,
                              const float* __restrict__ bxh, const float* __restrict__ bhh) {
    int i = threadIdx.x;
    if (i < 256)      g_bzr[i] = bxz[i] + bhz[i];
    else if (i < 512) g_bzr[i] = bxr[i - 256] + bhr[i - 256];
    else              g_bh[i - 512] = bxh[i - 512] + bhh[i - 512];
}

// ---------------- SpMM (CSR gather, half in, half out, fp32 accumulate) ----------------
__global__ void spmm_h(const __half* __restrict__ V, __half* __restrict__ O) {
    int d = blockIdx.x;
    int c = threadIdx.x;
    int s0 = g_rowptr[d];
    int s1 = g_rowptr[d + 1];
    __shared__ int   ss[128];
    __shared__ float sv[128];
    float acc = 0.f;
    for (int base = s0; base < s1; base += 128) {
        int m = min(128, s1 - base);
        if (c < m) { ss[c] = g_srcs[base + c] << 8; sv[c] = g_vals[base + c]; }
        __syncthreads();
        int j = 0;
        for (; j + 4 <= m; j += 4) {
            float v0 = __half2float(V[ss[j]     + c]);
            float v1 = __half2float(V[ss[j + 1] + c]);
            float v2 = __half2float(V[ss[j + 2] + c]);
            float v3 = __half2float(V[ss[j + 3] + c]);
            acc = fmaf(sv[j], v0, acc);     acc = fmaf(sv[j + 1], v1, acc);
            acc = fmaf(sv[j + 2], v2, acc); acc = fmaf(sv[j + 3], v3, acc);
        }
        for (; j < m; j++) acc = fmaf(sv[j], __half2float(V[ss[j] + c]), acc);
        __syncthreads();
    }
    O[(size_t)d * 256 + c] = __float2half_rn(acc);
}

// ---------------- fp16 tensor-core GEMM (ldmatrix + cp.async) ----------------
// C[M, N] = concat_A[M, KTOT] @ B[KTOT, N]. A = up to 4 half [M,256] slabs along K.
// BM=128, BN=128, BK=64. 8 warps (4x2), warp tile 32x64, mma m16n8k16 f32.f16.
// MODE 0: Z=sigmoid -> C (cols<256); R=sigmoid, hr=aux1*R -> auxh (cols>=256)
// MODE 1: h0 = z*h + (1-z)*tanh(v) -> C ; relu(h0) -> auxh   (z=aux1, h=aux2)
// MODE 2: v + bias -> C  (ldc=128)
template <int KTOT, int MODE>
__global__ void __launch_bounds__(256, 1) gemmh(
    const __half* __restrict__ a0, const __half* __restrict__ a1,
    const __half* __restrict__ a2, const __half* __restrict__ a3,
    const __half* __restrict__ Bw, int Nw,
    const float* __restrict__ bias,
    float* __restrict__ C,
    const float* __restrict__ aux1, const float* __restrict__ aux2,
    __half* __restrict__ auxh)
{
    constexpr int NKT = KTOT / 64;
    extern __shared__ char smem[];
    // per buffer: A 16KB ([m][128B swizzled]), B 16KB ([k][256B swizzled]); 2 buffers
    uint32_t sb = smem_u32(smem);
    float* biass = (float*)(smem + 65536);
    int tid = threadIdx.x, wid = tid >> 5, lane = tid & 31;
    int row0 = blockIdx.y * 128;
    int col0 = blockIdx.x * 128;
    const __half* ap[4] = {a0, a1, a2, a3};

    if (tid < 128) biass[tid] = bias[col0 + tid];

    auto issue = [&](int kt, int b) {
        uint32_t abase = sb + b * 32768;
        uint32_t bbase = abase + 16384;
        const __half* A = ap[kt >> 2];
        int kb = (kt & 3) * 64;
        #pragma unroll
        for (int t = 0; t < 4; t++) {   // A: 1024 x 16B chunks
            int i = tid + t * 256;
            int m = i >> 3, c = i & 7;
            int gr = row0 + m;
            uint32_t dst = abase + m * 128 + ((c ^ (m & 7)) << 4);
            const __half* src = A + (size_t)min(gr, N_NODES - 1) * 256 + kb + c * 8;
            uint32_t sz = (gr < N_NODES) ? 16u : 0u;
            asm volatile("cp.async.cg.shared.global [%0], [%1], 16, %2;"
                :: "r"(dst), "l"(src), "r"(sz));
        }
        #pragma unroll
        for (int t = 0; t < 4; t++) {   // B: 64 rows x 16 chunks
            int i = tid + t * 256;
            int k = i >> 4, c = i & 15;
            uint32_t cp = (uint32_t)((c & 8) | ((c ^ (k & 7)) & 7));
            uint32_t dst = bbase + k * 256 + (cp << 4);
            const __half* src = Bw + (size_t)(kt * 64 + k) * Nw + col0 + c * 8;
            asm volatile("cp.async.cg.shared.global [%0], [%1], 16;"
                :: "r"(dst), "l"(src));
        }
        CP_COMMIT();
    };

    int wr = wid >> 1, wc = wid & 1;
    float acc[2][8][4];
    #pragma unroll
    for (int mt = 0; mt < 2; mt++)
        #pragma unroll
        for (int nt = 0; nt < 8; nt++)
            #pragma unroll
            for (int i = 0; i < 4; i++) acc[mt][nt][i] = 0.f;

    issue(0, 0);
    issue(1, 1);

    for (int kt = 0; kt < NKT; kt++) {
        int b = kt & 1;
        if (kt + 1 < NKT) asm volatile("cp.async.wait_group 1;" ::: "memory");
        else              asm volatile("cp.async.wait_group 0;" ::: "memory");
        __syncthreads();
        uint32_t abase = sb + b * 32768;
        uint32_t bbase = abase + 16384;
        #pragma unroll
        for (int ks = 0; ks < 4; ks++) {
            uint32_t af[2][4];
            #pragma unroll
            for (int mt = 0; mt < 2; mt++) {
                int m = wr * 32 + mt * 16 + (lane & 15);
                int c = ks * 2 + (lane >> 4);
                ldm_x4(af[mt], abase + m * 128 + ((c ^ (m & 7)) << 4));
            }
            uint32_t bf[4][4];
            #pragma unroll
            for (int nt2 = 0; nt2 < 4; nt2++) {
                int k = ks * 16 + (lane & 15);
                int c = ((wc * 64 + nt2 * 16) >> 3) + (lane >> 4);
                uint32_t cp = (uint32_t)((c & 8) | ((c ^ (k & 7)) & 7));
                ldm_x4_t(bf[nt2], bbase + k * 256 + (cp << 4));
            }
            #pragma unroll
            for (int mt = 0; mt < 2; mt++)
                #pragma unroll
                for (int nt2 = 0; nt2 < 4; nt2++) {
                    mma_f16(acc[mt][nt2 * 2],     af[mt], bf[nt2][0], bf[nt2][1]);
                    mma_f16(acc[mt][nt2 * 2 + 1], af[mt], bf[nt2][2], bf[nt2][3]);
                }
        }
        __syncthreads();
        if (kt + 2 < NKT) issue(kt + 2, b);
    }

    // epilogue
    int g = lane >> 2, tg = lane & 3;
    #pragma unroll
    for (int mt = 0; mt < 2; mt++) {
        #pragma unroll
        for (int hf = 0; hf < 2; hf++) {
            int gr = row0 + wr * 32 + mt * 16 + g + hf * 8;
            if (gr >= N_NODES) continue;
            #pragma unroll
            for (int nt = 0; nt < 8; nt++) {
                int lc = wc * 64 + nt * 8 + tg * 2;
                int gc = col0 + lc;
                float v0 = acc[mt][nt][hf * 2 + 0] + biass[lc];
                float v1 = acc[mt][nt][hf * 2 + 1] + biass[lc + 1];
                if (MODE == 0) {
                    float s0 = 1.f / (1.f + __expf(-v0));
                    float s1 = 1.f / (1.f + __expf(-v1));
                    if (gc < 256) {
                        *(float2*)(C + (size_t)gr * 256 + gc) = make_float2(s0, s1);
                    } else {
                        int cc = gc - 256;
                        float h0v = aux1[(size_t)gr * 256 + cc];
                        float h1v = aux1[(size_t)gr * 256 + cc + 1];
                        *(__half2*)(auxh + (size_t)gr * 256 + cc) =
                            __floats2half2_rn(h0v * s0, h1v * s1);
                    }
                } else if (MODE == 1) {
                    float t0 = 1.f - 2.f / (__expf(2.f * v0) + 1.f);
                    float t1 = 1.f - 2.f / (__expf(2.f * v1) + 1.f);
                    float z0 = aux1[(size_t)gr * 256 + gc];
                    float z1 = aux1[(size_t)gr * 256 + gc + 1];
                    float h0v = aux2[(size_t)gr * 256 + gc];
                    float h1v = aux2[(size_t)gr * 256 + gc + 1];
                    float o0 = z0 * h0v + (1.f - z0) * t0;
                    float o1 = z1 * h1v + (1.f - z1) * t1;
                    *(float2*)(C + (size_t)gr * 256 + gc) = make_float2(o0, o1);
                    *(__half2*)(auxh + (size_t)gr * 256 + gc) =
                        __floats2half2_rn(fmaxf(o0, 0.f), fmaxf(o1, 0.f));
                } else {
                    *(float2*)(C + (size_t)gr * 128 + gc) = make_float2(v0, v1);
                }
            }
        }
    }
}

// ---------------- launch ----------------
extern "C" void kernel_launch(void* const* d_in, const int* in_sizes, int n_in,
                              void* d_out, int out_size) {
    const float* x   = (const float*)d_in[0];
    const float* h   = (const float*)d_in[1];
    const int*   ei  = (const int*)d_in[2];
    const float* w   = (const float*)d_in[3];
    const float* Wxz = (const float*)d_in[4];  const float* bxz = (const float*)d_in[5];
    const float* Whz = (const float*)d_in[6];  const float* bhz = (const float*)d_in[7];
    const float* Wxr = (const float*)d_in[8];  const float* bxr = (const float*)d_in[9];
    const float* Whr = (const float*)d_in[10]; const float* bhr = (const float*)d_in[11];
    const float* Wxh = (const float*)d_in[12]; const float* bxh = (const float*)d_in[13];
    const float* Whh = (const float*)d_in[14]; const float* bhh = (const float*)d_in[15];
    const float* Wl  = (const float*)d_in[16]; const float* bl  = (const float*)d_in[17];

    float* out = (float*)d_out;                   // [N,128]
    float* h0  = out + (size_t)N_NODES * 128;     // [N,256]

    __half *p_xh, *p_hh, *p_Lxh, *p_Lhh, *p_hrh, *p_Lhrh, *p_h0rh;
    __half *p_Wzrh, *p_WhPh, *p_Wlth;
    float *p_Z, *p_bzr, *p_bh;
    cudaGetSymbolAddress((void**)&p_xh,   g_xh);
    cudaGetSymbolAddress((void**)&p_hh,   g_hh);
    cudaGetSymbolAddress((void**)&p_Lxh,  g_Lxh);
    cudaGetSymbolAddress((void**)&p_Lhh,  g_Lhh);
    cudaGetSymbolAddress((void**)&p_hrh,  g_hrh);
    cudaGetSymbolAddress((void**)&p_Lhrh, g_Lhrh);
    cudaGetSymbolAddress((void**)&p_h0rh, g_h0rh);
    cudaGetSymbolAddress((void**)&p_Z,    g_Z);
    cudaGetSymbolAddress((void**)&p_Wzrh, g_Wzrh);
    cudaGetSymbolAddress((void**)&p_WhPh, g_WhPh);
    cudaGetSymbolAddress((void**)&p_Wlth, g_Wlth);
    cudaGetSymbolAddress((void**)&p_bzr,  g_bzr);
    cudaGetSymbolAddress((void**)&p_bh,   g_bh);

    const int SMEM_TOT = 65536 + 512;
    cudaFuncSetAttribute(gemmh<1024, 0>, cudaFuncAttributeMaxDynamicSharedMemorySize, SMEM_TOT);
    cudaFuncSetAttribute(gemmh<1024, 1>, cudaFuncAttributeMaxDynamicSharedMemorySize, SMEM_TOT);
    cudaFuncSetAttribute(gemmh<256, 2>,  cudaFuncAttributeMaxDynamicSharedMemorySize, SMEM_TOT);

    // graph normalization + CSR build
    zero_kernel<<<(N_NODES + 255) / 256, 256>>>();
    deg_hist_kernel<<<(N_EDGES + 255) / 256, 256>>>(ei, w);
    dis_kernel<<<(N_NODES + 255) / 256, 256>>>();
    scan_kernel<<<1, 1024>>>();
    scatter_kernel<<<(N_EDGES + 255) / 256, 256>>>(ei, w);

    // fp16 conversions + packed weights
    cvt_kernel<<<(N_NODES * 256 + 255) / 256, 256>>>(x, h);
    pack_w_kernel<<<(1024 * 512 + 1024 * 256 + 256 * 128 + 255) / 256, 256>>>(
        Wxz, Whz, Wxr, Whr, Wxh, Whh, Wl);
    pack_b_kernel<<<1, 768>>>(bxz, bhz, bxr, bhr, bxh, bhh);

    // SpMMs: Lx, Lh
    spmm_h<<<N_NODES, 256>>>(p_xh, p_Lxh);
    spmm_h<<<N_NODES, 256>>>(p_hh, p_Lhh);

    int gy = (N_NODES + 127) / 128;   // 157

    // GEMM1: [x|Lx|h|Lh] @ Wzr -> Z (g_Z fp32) + hr=h*R (g_hrh half)
    {
        dim3 grid(4, gy);
        gemmh<1024, 0><<<grid, 256, SMEM_TOT>>>(
            p_xh, p_Lxh, p_hh, p_Lhh, p_Wzrh, 512, p_bzr, p_Z, h, nullptr, p_hrh);
    }

    // L(hr)
    spmm_h<<<N_NODES, 256>>>(p_hrh, p_Lhrh);

    // GEMM2: h0 = Z*h + (1-Z)*tanh([x|Lx|hr|Lhr] @ WhP + bh); relu(h0) -> half
    {
        dim3 grid(2, gy);
        gemmh<1024, 1><<<grid, 256, SMEM_TOT>>>(
            p_xh, p_Lxh, p_hrh, p_Lhrh, p_WhPh, 256, p_bh, h0, p_Z, h, p_h0rh);
    }

    // GEMM3: out = relu(h0) @ Wl + bl
    {
        dim3 grid(1, gy);
        gemmh<256, 2><<<grid, 256, SMEM_TOT>>>(
            p_h0rh, p_h0rh, p_h0rh, p_h0rh, p_Wlth, 128, bl, out, nullptr, nullptr, nullptr);
    }
}

// round 5
// speedup vs baseline: 3.7824x; 1.3751x over previous
#include <cuda_runtime.h>
#include <cuda_fp16.h>
#include <math.h>
#include <stdint.h>

#define N_NODES 20000
#define N_EDGES 320000

// ---------------- PTX helpers ----------------
__device__ __forceinline__ uint32_t smem_u32(const void* p) {
    uint32_t a;
    asm("{ .reg .u64 t; cvta.to.shared.u64 t, %1; cvt.u32.u64 %0, t; }" : "=r"(a) : "l"(p));
    return a;
}
__device__ __forceinline__ void ldm_x4(uint32_t r[4], uint32_t addr) {
    asm volatile("ldmatrix.sync.aligned.m8n8.x4.shared.b16 {%0,%1,%2,%3}, [%4];"
        : "=r"(r[0]), "=r"(r[1]), "=r"(r[2]), "=r"(r[3]) : "r"(addr));
}
__device__ __forceinline__ void ldm_x4_t(uint32_t r[4], uint32_t addr) {
    asm volatile("ldmatrix.sync.aligned.m8n8.x4.trans.shared.b16 {%0,%1,%2,%3}, [%4];"
        : "=r"(r[0]), "=r"(r[1]), "=r"(r[2]), "=r"(r[3]) : "r"(addr));
}
__device__ __forceinline__ void mma_f16(float* c, const uint32_t a[4], uint32_t b0, uint32_t b1) {
    asm volatile(
        "mma.sync.aligned.m16n8k16.row.col.f32.f16.f16.f32 "
        "{%0,%1,%2,%3},{%4,%5,%6,%7},{%8,%9},{%0,%1,%2,%3};"
        : "+f"(c[0]), "+f"(c[1]), "+f"(c[2]), "+f"(c[3])
        : "r"(a[0]), "r"(a[1]), "r"(a[2]), "r"(a[3]), "r"(b0), "r"(b1));
}
#define CP_COMMIT() asm volatile("cp.async.commit_group;" ::: "memory")

// ---------------- scratch ----------------
__device__ float g_deg[N_NODES];
__device__ float g_dis[N_NODES];
__device__ int   g_cnt[N_NODES];
__device__ int   g_cur[N_NODES];
__device__ int   g_rowptr[N_NODES + 1];
__device__ int   g_srcs[N_EDGES];
__device__ float g_vals[N_EDGES];

__device__ __align__(16) __half g_xh  [(size_t)N_NODES * 256];
__device__ __align__(16) __half g_hh  [(size_t)N_NODES * 256];
__device__ __align__(16) __half g_Lxh [(size_t)N_NODES * 256];
__device__ __align__(16) __half g_Lhh [(size_t)N_NODES * 256];
__device__ __align__(16) __half g_hrh [(size_t)N_NODES * 256];
__device__ __align__(16) __half g_Lhrh[(size_t)N_NODES * 256];
__device__ __align__(16) __half g_h0rh[(size_t)N_NODES * 256];
__device__ __align__(16) __half g_Zh  [(size_t)N_NODES * 256];

__device__ __align__(16) __half g_Wzrh[1024 * 512];   // [K=1024][N=512]
__device__ __align__(16) __half g_WhPh[1024 * 256];   // [K=1024][N=256]
__device__ __align__(16) __half g_Wlth[256 * 128];    // [K=256][N=128]
__device__ float g_bzr[512];
__device__ float g_bh[256];

// ---------------- setup kernels ----------------
__global__ void zero_kernel() {
    int i = blockIdx.x * blockDim.x + threadIdx.x;
    if (i < N_NODES) { g_deg[i] = 0.f; g_cnt[i] = 0; g_cur[i] = 0; }
}

__global__ void deg_hist_kernel(const int* __restrict__ ei, const float* __restrict__ w) {
    int e = blockIdx.x * blockDim.x + threadIdx.x;
    if (e < N_EDGES) {
        atomicAdd(&g_deg[ei[e]], w[e]);
        atomicAdd(&g_cnt[ei[N_EDGES + e]], 1);
    }
}

// scan (coalesced smem staging) + dis computation fused
__global__ void scan_kernel() {
    extern __shared__ int sh[];
    __shared__ int warp_sums[32];
    const int PER = 20;
    int tid = threadIdx.x;
    // fused dis
    for (int i = tid; i < N_NODES; i += 1024) {
        float dg = g_deg[i];
        g_dis[i] = (dg > 0.f) ? rsqrtf(dg) : 0.f;
    }
    // coalesced stage of counts
    for (int i = tid; i < N_NODES; i += 1024) sh[i] = g_cnt[i];
    __syncthreads();
    int base = tid * PER;
    int loc[PER];
    int s = 0;
    #pragma unroll
    for (int i = 0; i < PER; i++) {
        int idx = base + i;
        int v = (idx < N_NODES) ? sh[idx] : 0;
        loc[i] = s; s += v;
    }
    int lane = tid & 31, wid = tid >> 5;
    int v = s;
    #pragma unroll
    for (int o = 1; o < 32; o <<= 1) {
        int t = __shfl_up_sync(0xFFFFFFFFu, v, o);
        if (lane >= o) v += t;
    }
    if (lane == 31) warp_sums[wid] = v;
    __syncthreads();
    if (wid == 0) {
        int wv = warp_sums[lane];
        #pragma unroll
        for (int o = 1; o < 32; o <<= 1) {
            int t = __shfl_up_sync(0xFFFFFFFFu, wv, o);
            if (lane >= o) wv += t;
        }
        warp_sums[lane] = wv;
    }
    __syncthreads();
    int ex = v - s + (wid ? warp_sums[wid - 1] : 0);
    #pragma unroll
    for (int i = 0; i < PER; i++) {
        int idx = base + i;
        if (idx < N_NODES) g_rowptr[idx] = ex + loc[i];
    }
    if (tid == 1023) g_rowptr[N_NODES] = ex + s;
}

__global__ void scatter_kernel(const int* __restrict__ ei, const float* __restrict__ w) {
    int e = blockIdx.x * blockDim.x + threadIdx.x;
    if (e < N_EDGES) {
        int s = ei[e];
        int d = ei[N_EDGES + e];
        int pos = g_rowptr[d] + atomicAdd(&g_cur[d], 1);
        g_srcs[pos] = s;
        g_vals[pos] = -g_dis[s] * w[e] * g_dis[d];
    }
}

// fused: cvt x/h to half + pack all weights (half, [K][N]) + pack biases
__global__ void setup_all(const float* __restrict__ x, const float* __restrict__ h,
                          const float* __restrict__ Wxz, const float* __restrict__ Whz,
                          const float* __restrict__ Wxr, const float* __restrict__ Whr,
                          const float* __restrict__ Wxh, const float* __restrict__ Whh,
                          const float* __restrict__ Wl,
                          const float* __restrict__ bxz, const float* __restrict__ bhz,
                          const float* __restrict__ bxr, const float* __restrict__ bhr,
                          const float* __restrict__ bxh, const float* __restrict__ bhh) {
    int i = blockIdx.x * blockDim.x + threadIdx.x;
    if (i < N_NODES * 256) {
        g_xh[i] = __float2half_rn(x[i]);
        g_hh[i] = __float2half_rn(h[i]);
    }
    if (i < 1024 * 512) {
        int k = i >> 9, j = i & 511;
        int jj = j & 255;
        const float* Wx = (j < 256) ? Wxz : Wxr;
        const float* Wh = (j < 256) ? Whz : Whr;
        float v;
        if (k < 512) v = Wx[((k >= 256) ? 65536 : 0) + (k & 255) * 256 + jj];
        else         v = Wh[((k >= 768) ? 65536 : 0) + (k & 255) * 256 + jj];
        g_Wzrh[i] = __float2half_rn(v);
        if (i < 1024 * 256) {
            int k2 = i >> 8, jj2 = i & 255;
            float v2;
            if (k2 < 512) v2 = Wxh[((k2 >= 256) ? 65536 : 0) + (k2 & 255) * 256 + jj2];
            else          v2 = Whh[((k2 >= 768) ? 65536 : 0) + (k2 & 255) * 256 + jj2];
            g_WhPh[i] = __float2half_rn(v2);
        }
        if (i < 256 * 128) g_Wlth[i] = __float2half_rn(Wl[i]);
        if (i < 512) {
            if (i < 256) { g_bzr[i] = bxz[i] + bhz[i]; g_bh[i] = bxh[i] + bhh[i]; }
            else          g_bzr[i] = bxr[i - 256] + bhr[i - 256];
        }
    }
}

// ---------------- SpMM: fused Lx+Lh (one pass over edges), half2 lanes ----------------
__global__ void spmm2(const __half2* __restrict__ X, const __half2* __restrict__ H,
                      __half2* __restrict__ OX, __half2* __restrict__ OH) {
    int d = blockIdx.x;
    int tid = threadIdx.x;          // 256
    int c = tid & 127;              // half2 feature index
    const __half2* V = (tid < 128) ? X : H;
    __half2* O = (tid < 128) ? OX : OH;
    int s0 = g_rowptr[d], s1 = g_rowptr[d + 1];
    __shared__ int   ss[128];
    __shared__ float sv[128];
    float ax = 0.f, ay = 0.f;
    for (int base = s0; base < s1; base += 128) {
        int m = min(128, s1 - base);
        if (tid < m) { ss[tid] = g_srcs[base + tid] << 7; sv[tid] = g_vals[base + tid]; }
        __syncthreads();
        int j = 0;
        for (; j + 4 <= m; j += 4) {
            float2 f0 = __half22float2(V[ss[j]     + c]);
            float2 f1 = __half22float2(V[ss[j + 1] + c]);
            float2 f2 = __half22float2(V[ss[j + 2] + c]);
            float2 f3 = __half22float2(V[ss[j + 3] + c]);
            ax = fmaf(sv[j], f0.x, ax);     ay = fmaf(sv[j], f0.y, ay);
            ax = fmaf(sv[j + 1], f1.x, ax); ay = fmaf(sv[j + 1], f1.y, ay);
            ax = fmaf(sv[j + 2], f2.x, ax); ay = fmaf(sv[j + 2], f2.y, ay);
            ax = fmaf(sv[j + 3], f3.x, ax); ay = fmaf(sv[j + 3], f3.y, ay);
        }
        for (; j < m; j++) {
            float2 f = __half22float2(V[ss[j] + c]);
            ax = fmaf(sv[j], f.x, ax); ay = fmaf(sv[j], f.y, ay);
        }
        __syncthreads();
    }
    O[d * 128 + c] = __floats2half2_rn(ax, ay);
}

// single-matrix SpMM (for Lhr), 128 threads half2
__global__ void spmm1(const __half2* __restrict__ V, __half2* __restrict__ O) {
    int d = blockIdx.x;
    int c = threadIdx.x;            // 128
    int s0 = g_rowptr[d], s1 = g_rowptr[d + 1];
    __shared__ int   ss[128];
    __shared__ float sv[128];
    float ax = 0.f, ay = 0.f;
    for (int base = s0; base < s1; base += 128) {
        int m = min(128, s1 - base);
        if (c < m) { ss[c] = g_srcs[base + c] << 7; sv[c] = g_vals[base + c]; }
        __syncthreads();
        int j = 0;
        for (; j + 4 <= m; j += 4) {
            float2 f0 = __half22float2(V[ss[j]     + c]);
            float2 f1 = __half22float2(V[ss[j + 1] + c]);
            float2 f2 = __half22float2(V[ss[j + 2] + c]);
            float2 f3 = __half22float2(V[ss[j + 3] + c]);
            ax = fmaf(sv[j], f0.x, ax);     ay = fmaf(sv[j], f0.y, ay);
            ax = fmaf(sv[j + 1], f1.x, ax); ay = fmaf(sv[j + 1], f1.y, ay);
            ax = fmaf(sv[j + 2], f2.x, ax); ay = fmaf(sv[j + 2], f2.y, ay);
            ax = fmaf(sv[j + 3], f3.x, ax); ay = fmaf(sv[j + 3], f3.y, ay);
        }
        for (; j < m; j++) {
            float2 f = __half22float2(V[ss[j] + c]);
            ax = fmaf(sv[j], f.x, ax); ay = fmaf(sv[j], f.y, ay);
        }
        __syncthreads();
    }
    O[d * 128 + c] = __floats2half2_rn(ax, ay);
}

// ---------------- fp16 tensor-core GEMM, 3-stage cp.async ----------------
// BM=128, BN=128, BK=64. 8 warps (4x2), warp tile 32x64, mma m16n8k16.
// MODE 0: Z=sigmoid -> Zh (cols<256); R=sigmoid, hr=hfull*R -> auxh (cols>=256)
// MODE 1: h0 = z*hfull + (1-z)*tanh(v) -> C(fp32,ldc256); relu(h0) -> auxh
// MODE 2: v + bias -> C (fp32, ldc=128)
template <int KTOT, int MODE>
__global__ void __launch_bounds__(256, 2) gemmh(
    const __half* __restrict__ a0, const __half* __restrict__ a1,
    const __half* __restrict__ a2, const __half* __restrict__ a3,
    const __half* __restrict__ Bw, int Nw,
    const float* __restrict__ bias,
    float* __restrict__ C,
    const float* __restrict__ hfull,
    __half* __restrict__ Zh,
    __half* __restrict__ auxh)
{
    constexpr int NKT = KTOT / 64;
    extern __shared__ char smem[];
    uint32_t sb = smem_u32(smem);
    float* biass = (float*)(smem + 98304);
    int tid = threadIdx.x, wid = tid >> 5, lane = tid & 31;
    int row0 = blockIdx.y * 128;
    int col0 = blockIdx.x * 128;
    const __half* ap[4] = {a0, a1, a2, a3};

    if (tid < 128) biass[tid] = bias[col0 + tid];

    auto issue = [&](int kt, int b) {
        uint32_t abase = sb + b * 32768;
        uint32_t bbase = abase + 16384;
        const __half* A = ap[(kt >> 2) & 3];
        int kb = (kt & 3) * 64;
        #pragma unroll
        for (int t = 0; t < 4; t++) {   // A: 128 rows x 8 chunks of 16B
            int i = tid + t * 256;
            int m = i >> 3, c = i & 7;
            int gr = row0 + m;
            uint32_t dst = abase + m * 128 + ((c ^ (m & 7)) << 4);
            const __half* src = A + (size_t)min(gr, N_NODES - 1) * 256 + kb + c * 8;
            uint32_t sz = (gr < N_NODES) ? 16u : 0u;
            asm volatile("cp.async.cg.shared.global [%0], [%1], 16, %2;"
                :: "r"(dst), "l"(src), "r"(sz));
        }
        #pragma unroll
        for (int t = 0; t < 4; t++) {   // B: 64 rows x 16 chunks
            int i = tid + t * 256;
            int k = i >> 4, c = i & 15;
            uint32_t cp = (uint32_t)((c & 8) | ((c ^ (k & 7)) & 7));
            uint32_t dst = bbase + k * 256 + (cp << 4);
            const __half* src = Bw + (size_t)(kt * 64 + k) * Nw + col0 + c * 8;
            asm volatile("cp.async.cg.shared.global [%0], [%1], 16;"
                :: "r"(dst), "l"(src));
        }
        CP_COMMIT();
    };

    int wr = wid >> 1, wc = wid & 1;
    float acc[2][8][4];
    #pragma unroll
    for (int mt = 0; mt < 2; mt++)
        #pragma unroll
        for (int nt = 0; nt < 8; nt++)
            #pragma unroll
            for (int i = 0; i < 4; i++) acc[mt][nt][i] = 0.f;

    issue(0, 0);
    issue(1, 1);
    issue(2, 2);

    for (int kt = 0; kt < NKT; kt++) {
        int b = kt % 3;
        if (kt + 3 <= NKT)      asm volatile("cp.async.wait_group 2;" ::: "memory");
        else if (kt + 2 == NKT) asm volatile("cp.async.wait_group 1;" ::: "memory");
        else                    asm volatile("cp.async.wait_group 0;" ::: "memory");
        __syncthreads();
        uint32_t abase = sb + b * 32768;
        uint32_t bbase = abase + 16384;
        #pragma unroll
        for (int ks = 0; ks < 4; ks++) {
            uint32_t af[2][4];
            #pragma unroll
            for (int mt = 0; mt < 2; mt++) {
                int m = wr * 32 + mt * 16 + (lane & 15);
                int c = ks * 2 + (lane >> 4);
                ldm_x4(af[mt], abase + m * 128 + ((c ^ (m & 7)) << 4));
            }
            uint32_t bf[4][4];
            #pragma unroll
            for (int nt2 = 0; nt2 < 4; nt2++) {
                int k = ks * 16 + (lane & 15);
                int c = ((wc * 64 + nt2 * 16) >> 3) + (lane >> 4);
                uint32_t cp = (uint32_t)((c & 8) | ((c ^ (k & 7)) & 7));
                ldm_x4_t(bf[nt2], bbase + k * 256 + (cp << 4));
            }
            #pragma unroll
            for (int mt = 0; mt < 2; mt++)
                #pragma unroll
                for (int nt2 = 0; nt2 < 4; nt2++) {
                    mma_f16(acc[mt][nt2 * 2],     af[mt], bf[nt2][0], bf[nt2][1]);
                    mma_f16(acc[mt][nt2 * 2 + 1], af[mt], bf[nt2][2], bf[nt2][3]);
                }
        }
        __syncthreads();
        if (kt + 3 < NKT) issue(kt + 3, b);
    }

    // epilogue
    int g = lane >> 2, tg = lane & 3;
    #pragma unroll
    for (int mt = 0; mt < 2; mt++) {
        #pragma unroll
        for (int hf = 0; hf < 2; hf++) {
            int gr = row0 + wr * 32 + mt * 16 + g + hf * 8;
            if (gr >= N_NODES) continue;
            #pragma unroll
            for (int nt = 0; nt < 8; nt++) {
                int lc = wc * 64 + nt * 8 + tg * 2;
                int gc = col0 + lc;
                float v0 = acc[mt][nt][hf * 2 + 0] + biass[lc];
                float v1 = acc[mt][nt][hf * 2 + 1] + biass[lc + 1];
                if (MODE == 0) {
                    float s0 = 1.f / (1.f + __expf(-v0));
                    float s1 = 1.f / (1.f + __expf(-v1));
                    if (gc < 256) {
                        *(__half2*)(Zh + (size_t)gr * 256 + gc) = __floats2half2_rn(s0, s1);
                    } else {
                        int cc = gc - 256;
                        float h0v = hfull[(size_t)gr * 256 + cc];
                        float h1v = hfull[(size_t)gr * 256 + cc + 1];
                        *(__half2*)(auxh + (size_t)gr * 256 + cc) =
                            __floats2half2_rn(h0v * s0, h1v * s1);
                    }
                } else if (MODE == 1) {
                    float t0 = 1.f - 2.f / (__expf(2.f * v0) + 1.f);
                    float t1 = 1.f - 2.f / (__expf(2.f * v1) + 1.f);
                    float2 z = __half22float2(*(const __half2*)(Zh + (size_t)gr * 256 + gc));
                    float h0v = hfull[(size_t)gr * 256 + gc];
                    float h1v = hfull[(size_t)gr * 256 + gc + 1];
                    float o0 = z.x * h0v + (1.f - z.x) * t0;
                    float o1 = z.y * h1v + (1.f - z.y) * t1;
                    *(float2*)(C + (size_t)gr * 256 + gc) = make_float2(o0, o1);
                    *(__half2*)(auxh + (size_t)gr * 256 + gc) =
                        __floats2half2_rn(fmaxf(o0, 0.f), fmaxf(o1, 0.f));
                } else {
                    *(float2*)(C + (size_t)gr * 128 + gc) = make_float2(v0, v1);
                }
            }
        }
    }
}

// ---------------- launch ----------------
extern "C" void kernel_launch(void* const* d_in, const int* in_sizes, int n_in,
                              void* d_out, int out_size) {
    const float* x   = (const float*)d_in[0];
    const float* h   = (const float*)d_in[1];
    const int*   ei  = (const int*)d_in[2];
    const float* w   = (const float*)d_in[3];
    const float* Wxz = (const float*)d_in[4];  const float* bxz = (const float*)d_in[5];
    const float* Whz = (const float*)d_in[6];  const float* bhz = (const float*)d_in[7];
    const float* Wxr = (const float*)d_in[8];  const float* bxr = (const float*)d_in[9];
    const float* Whr = (const float*)d_in[10]; const float* bhr = (const float*)d_in[11];
    const float* Wxh = (const float*)d_in[12]; const float* bxh = (const float*)d_in[13];
    const float* Whh = (const float*)d_in[14]; const float* bhh = (const float*)d_in[15];
    const float* Wl  = (const float*)d_in[16]; const float* bl  = (const float*)d_in[17];

    float* out = (float*)d_out;                   // [N,128]
    float* h0  = out + (size_t)N_NODES * 128;     // [N,256]

    __half *p_xh, *p_hh, *p_Lxh, *p_Lhh, *p_hrh, *p_Lhrh, *p_h0rh, *p_Zh;
    __half *p_Wzrh, *p_WhPh, *p_Wlth;
    float *p_bzr, *p_bh;
    cudaGetSymbolAddress((void**)&p_xh,   g_xh);
    cudaGetSymbolAddress((void**)&p_hh,   g_hh);
    cudaGetSymbolAddress((void**)&p_Lxh,  g_Lxh);
    cudaGetSymbolAddress((void**)&p_Lhh,  g_Lhh);
    cudaGetSymbolAddress((void**)&p_hrh,  g_hrh);
    cudaGetSymbolAddress((void**)&p_Lhrh, g_Lhrh);
    cudaGetSymbolAddress((void**)&p_h0rh, g_h0rh);
    cudaGetSymbolAddress((void**)&p_Zh,   g_Zh);
    cudaGetSymbolAddress((void**)&p_Wzrh, g_Wzrh);
    cudaGetSymbolAddress((void**)&p_WhPh, g_WhPh);
    cudaGetSymbolAddress((void**)&p_Wlth, g_Wlth);
    cudaGetSymbolAddress((void**)&p_bzr,  g_bzr);
    cudaGetSymbolAddress((void**)&p_bh,   g_bh);

    const int SMEM_TOT = 98304 + 512;
    cudaFuncSetAttribute(gemmh<1024, 0>, cudaFuncAttributeMaxDynamicSharedMemorySize, SMEM_TOT);
    cudaFuncSetAttribute(gemmh<1024, 1>, cudaFuncAttributeMaxDynamicSharedMemorySize, SMEM_TOT);
    cudaFuncSetAttribute(gemmh<256, 2>,  cudaFuncAttributeMaxDynamicSharedMemorySize, SMEM_TOT);
    cudaFuncSetAttribute(scan_kernel, cudaFuncAttributeMaxDynamicSharedMemorySize, 80000);

    // graph normalization + CSR build
    zero_kernel<<<(N_NODES + 255) / 256, 256>>>();
    deg_hist_kernel<<<(N_EDGES + 255) / 256, 256>>>(ei, w);
    scan_kernel<<<1, 1024, 80000>>>();
    scatter_kernel<<<(N_EDGES + 255) / 256, 256>>>(ei, w);

    // fused cvt + weight/bias packing
    setup_all<<<(N_NODES * 256 + 255) / 256, 256>>>(
        x, h, Wxz, Whz, Wxr, Whr, Wxh, Whh, Wl, bxz, bhz, bxr, bhr, bxh, bhh);

    // fused SpMM: Lx and Lh in one pass
    spmm2<<<N_NODES, 256>>>((const __half2*)p_xh, (const __half2*)p_hh,
                            (__half2*)p_Lxh, (__half2*)p_Lhh);

    int gy = (N_NODES + 127) / 128;   // 157

    // GEMM1: [x|Lx|h|Lh] @ Wzr -> Zh (half) + hr=h*R (half)
    {
        dim3 grid(4, gy);
        gemmh<1024, 0><<<grid, 256, SMEM_TOT>>>(
            p_xh, p_Lxh, p_hh, p_Lhh, p_Wzrh, 512, p_bzr, nullptr, h, p_Zh, p_hrh);
    }

    // L(hr)
    spmm1<<<N_NODES, 128>>>((const __half2*)p_hrh, (__half2*)p_Lhrh);

    // GEMM2: h0 = Z*h + (1-Z)*tanh([x|Lx|hr|Lhr] @ WhP + bh); relu(h0) -> half
    {
        dim3 grid(2, gy);
        gemmh<1024, 1><<<grid, 256, SMEM_TOT>>>(
            p_xh, p_Lxh, p_hrh, p_Lhrh, p_WhPh, 256, p_bh, h0, h, p_Zh, p_h0rh);
    }

    // GEMM3: out = relu(h0) @ Wl + bl
    {
        dim3 grid(1, gy);
        gemmh<256, 2><<<grid, 256, SMEM_TOT>>>(
            p_h0rh, p_h0rh, p_h0rh, p_h0rh, p_Wlth, 128, bl, out, nullptr, nullptr, nullptr);
    }
}

// round 6
// speedup vs baseline: 4.3191x; 1.1419x over previous
#include <cuda_runtime.h>
#include <cuda_fp16.h>
#include <math.h>
#include <stdint.h>

#define N_NODES 20000
#define N_EDGES 320000

// ---------------- PTX helpers ----------------
__device__ __forceinline__ uint32_t smem_u32(const void* p) {
    uint32_t a;
    asm("{ .reg .u64 t; cvta.to.shared.u64 t, %1; cvt.u32.u64 %0, t; }" : "=r"(a) : "l"(p));
    return a;
}
__device__ __forceinline__ void ldm_x4(uint32_t r[4], uint32_t addr) {
    asm volatile("ldmatrix.sync.aligned.m8n8.x4.shared.b16 {%0,%1,%2,%3}, [%4];"
        : "=r"(r[0]), "=r"(r[1]), "=r"(r[2]), "=r"(r[3]) : "r"(addr));
}
__device__ __forceinline__ void ldm_x4_t(uint32_t r[4], uint32_t addr) {
    asm volatile("ldmatrix.sync.aligned.m8n8.x4.trans.shared.b16 {%0,%1,%2,%3}, [%4];"
        : "=r"(r[0]), "=r"(r[1]), "=r"(r[2]), "=r"(r[3]) : "r"(addr));
}
__device__ __forceinline__ void mma_f16(float* c, const uint32_t a[4], uint32_t b0, uint32_t b1) {
    asm volatile(
        "mma.sync.aligned.m16n8k16.row.col.f32.f16.f16.f32 "
        "{%0,%1,%2,%3},{%4,%5,%6,%7},{%8,%9},{%0,%1,%2,%3};"
        : "+f"(c[0]), "+f"(c[1]), "+f"(c[2]), "+f"(c[3])
        : "r"(a[0]), "r"(a[1]), "r"(a[2]), "r"(a[3]), "r"(b0), "r"(b1));
}
#define CP_COMMIT() asm volatile("cp.async.commit_group;" ::: "memory")

// ---------------- scratch ----------------
__device__ float g_deg[N_NODES];
__device__ float g_dis[N_NODES];
__device__ int   g_cnt[N_NODES];
__device__ int   g_cur[N_NODES];
__device__ int   g_rowptr[N_NODES + 1];
__device__ int   g_srcs[N_EDGES];
__device__ float g_vals[N_EDGES];

__device__ __align__(16) __half g_xh  [(size_t)N_NODES * 256];
__device__ __align__(16) __half g_hh  [(size_t)N_NODES * 256];
__device__ __align__(16) __half g_Lxh [(size_t)N_NODES * 256];
__device__ __align__(16) __half g_Lhh [(size_t)N_NODES * 256];
__device__ __align__(16) __half g_hrh [(size_t)N_NODES * 256];
__device__ __align__(16) __half g_Lhrh[(size_t)N_NODES * 256];
__device__ __align__(16) __half g_h0rh[(size_t)N_NODES * 256];
__device__ __align__(16) __half g_Zh  [(size_t)N_NODES * 256];

__device__ __align__(16) __half g_Wzrh[1024 * 512];   // [K=1024][N=512]
__device__ __align__(16) __half g_WhPh[1024 * 256];   // [K=1024][N=256]
__device__ __align__(16) __half g_Wlth[256 * 128];    // [K=256][N=128]
__device__ float g_bzr[512];
__device__ float g_bh[256];

// ---------------- setup kernels ----------------
__global__ void zero_kernel() {
    int i = blockIdx.x * blockDim.x + threadIdx.x;
    if (i < N_NODES) { g_deg[i] = 0.f; g_cnt[i] = 0; g_cur[i] = 0; }
}

__global__ void deg_hist_kernel(const int* __restrict__ ei, const float* __restrict__ w) {
    int e = blockIdx.x * blockDim.x + threadIdx.x;
    if (e < N_EDGES) {
        atomicAdd(&g_deg[ei[e]], w[e]);
        atomicAdd(&g_cnt[ei[N_EDGES + e]], 1);
    }
}

// scan (coalesced smem staging) + dis computation fused
__global__ void scan_kernel() {
    extern __shared__ int sh[];
    __shared__ int warp_sums[32];
    const int PER = 20;
    int tid = threadIdx.x;
    for (int i = tid; i < N_NODES; i += 1024) {
        float dg = g_deg[i];
        g_dis[i] = (dg > 0.f) ? rsqrtf(dg) : 0.f;
    }
    for (int i = tid; i < N_NODES; i += 1024) sh[i] = g_cnt[i];
    __syncthreads();
    int base = tid * PER;
    int loc[PER];
    int s = 0;
    #pragma unroll
    for (int i = 0; i < PER; i++) {
        int idx = base + i;
        int v = (idx < N_NODES) ? sh[idx] : 0;
        loc[i] = s; s += v;
    }
    int lane = tid & 31, wid = tid >> 5;
    int v = s;
    #pragma unroll
    for (int o = 1; o < 32; o <<= 1) {
        int t = __shfl_up_sync(0xFFFFFFFFu, v, o);
        if (lane >= o) v += t;
    }
    if (lane == 31) warp_sums[wid] = v;
    __syncthreads();
    if (wid == 0) {
        int wv = warp_sums[lane];
        #pragma unroll
        for (int o = 1; o < 32; o <<= 1) {
            int t = __shfl_up_sync(0xFFFFFFFFu, wv, o);
            if (lane >= o) wv += t;
        }
        warp_sums[lane] = wv;
    }
    __syncthreads();
    int ex = v - s + (wid ? warp_sums[wid - 1] : 0);
    #pragma unroll
    for (int i = 0; i < PER; i++) {
        int idx = base + i;
        if (idx < N_NODES) g_rowptr[idx] = ex + loc[i];
    }
    if (tid == 1023) g_rowptr[N_NODES] = ex + s;
}

__global__ void scatter_kernel(const int* __restrict__ ei, const float* __restrict__ w) {
    int e = blockIdx.x * blockDim.x + threadIdx.x;
    if (e < N_EDGES) {
        int s = ei[e];
        int d = ei[N_EDGES + e];
        int pos = g_rowptr[d] + atomicAdd(&g_cur[d], 1);
        g_srcs[pos] = s;
        g_vals[pos] = -g_dis[s] * w[e] * g_dis[d];
    }
}

// fused: cvt x/h to half + pack all weights + biases
__global__ void setup_all(const float* __restrict__ x, const float* __restrict__ h,
                          const float* __restrict__ Wxz, const float* __restrict__ Whz,
                          const float* __restrict__ Wxr, const float* __restrict__ Whr,
                          const float* __restrict__ Wxh, const float* __restrict__ Whh,
                          const float* __restrict__ Wl,
                          const float* __restrict__ bxz, const float* __restrict__ bhz,
                          const float* __restrict__ bxr, const float* __restrict__ bhr,
                          const float* __restrict__ bxh, const float* __restrict__ bhh) {
    int i = blockIdx.x * blockDim.x + threadIdx.x;
    if (i < N_NODES * 256) {
        g_xh[i] = __float2half_rn(x[i]);
        g_hh[i] = __float2half_rn(h[i]);
    }
    if (i < 1024 * 512) {
        int k = i >> 9, j = i & 511;
        int jj = j & 255;
        const float* Wx = (j < 256) ? Wxz : Wxr;
        const float* Wh = (j < 256) ? Whz : Whr;
        float v;
        if (k < 512) v = Wx[((k >= 256) ? 65536 : 0) + (k & 255) * 256 + jj];
        else         v = Wh[((k >= 768) ? 65536 : 0) + (k & 255) * 256 + jj];
        g_Wzrh[i] = __float2half_rn(v);
        if (i < 1024 * 256) {
            int k2 = i >> 8, jj2 = i & 255;
            float v2;
            if (k2 < 512) v2 = Wxh[((k2 >= 256) ? 65536 : 0) + (k2 & 255) * 256 + jj2];
            else          v2 = Whh[((k2 >= 768) ? 65536 : 0) + (k2 & 255) * 256 + jj2];
            g_WhPh[i] = __float2half_rn(v2);
        }
        if (i < 256 * 128) g_Wlth[i] = __float2half_rn(Wl[i]);
        if (i < 512) {
            if (i < 256) { g_bzr[i] = bxz[i] + bhz[i]; g_bh[i] = bxh[i] + bhh[i]; }
            else          g_bzr[i] = bxr[i - 256] + bhr[i - 256];
        }
    }
}

// ---------------- SpMM: warp-per-row, shuffle-broadcast, no smem/barriers ----------------
// TWO=true: gather X and H simultaneously (shared index traffic).
template <bool TWO>
__global__ void __launch_bounds__(256) spmmw(
    const __half2* __restrict__ X, const __half2* __restrict__ H,
    __half2* __restrict__ OX, __half2* __restrict__ OH)
{
    int wid = threadIdx.x >> 5, lane = threadIdx.x & 31;
    int d = blockIdx.x * 8 + wid;
    if (d >= N_NODES) return;
    int s0 = g_rowptr[d], s1 = g_rowptr[d + 1];
    float ax[8] = {0.f, 0.f, 0.f, 0.f, 0.f, 0.f, 0.f, 0.f};
    float ah[8] = {0.f, 0.f, 0.f, 0.f, 0.f, 0.f, 0.f, 0.f};
    for (int base = s0; base < s1; base += 32) {
        int n = min(32, s1 - base);
        int idx = 0; float val = 0.f;
        if (lane < n) { idx = g_srcs[base + lane] << 7; val = g_vals[base + lane]; }
        for (int j = 0; j < n; j++) {
            int so  = __shfl_sync(0xFFFFFFFFu, idx, j);
            float v = __shfl_sync(0xFFFFFFFFu, val, j);
            #pragma unroll
            for (int k = 0; k < 4; k++) {
                float2 fx = __half22float2(X[so + lane + 32 * k]);
                ax[2 * k]     = fmaf(v, fx.x, ax[2 * k]);
                ax[2 * k + 1] = fmaf(v, fx.y, ax[2 * k + 1]);
                if (TWO) {
                    float2 fh = __half22float2(H[so + lane + 32 * k]);
                    ah[2 * k]     = fmaf(v, fh.x, ah[2 * k]);
                    ah[2 * k + 1] = fmaf(v, fh.y, ah[2 * k + 1]);
                }
            }
        }
    }
    #pragma unroll
    for (int k = 0; k < 4; k++) {
        OX[d * 128 + lane + 32 * k] = __floats2half2_rn(ax[2 * k], ax[2 * k + 1]);
        if (TWO) OH[d * 128 + lane + 32 * k] = __floats2half2_rn(ah[2 * k], ah[2 * k + 1]);
    }
}

// ---------------- fp16 tensor-core GEMM, BM=64 BN=128 BK=64, 3-stage, 3 CTA/SM ----------
// 8 warps (2x4), warp tile 32x32, mma m16n8k16.
// MODE 0: Z=sigmoid -> Zh (cols<256); R=sigmoid, hr=hfull*R -> auxh (cols>=256)
// MODE 1: h0 = z*hfull + (1-z)*tanh(v) -> C(fp32,ldc256); relu(h0) -> auxh
// MODE 2: v + bias -> C (fp32, ldc=128)
template <int KTOT, int MODE>
__global__ void __launch_bounds__(256, 3) gemmh(
    const __half* __restrict__ a0, const __half* __restrict__ a1,
    const __half* __restrict__ a2, const __half* __restrict__ a3,
    const __half* __restrict__ Bw, int Nw,
    const float* __restrict__ bias,
    float* __restrict__ C,
    const float* __restrict__ hfull,
    __half* __restrict__ Zh,
    __half* __restrict__ auxh)
{
    constexpr int NKT = KTOT / 64;
    constexpr int STAGE = 24576;        // A 8KB + B 16KB
    extern __shared__ char smem[];
    uint32_t sb = smem_u32(smem);
    float* biass = (float*)(smem + 3 * STAGE);
    int tid = threadIdx.x, wid = tid >> 5, lane = tid & 31;
    int row0 = blockIdx.y * 64;
    int col0 = blockIdx.x * 128;
    const __half* ap[4] = {a0, a1, a2, a3};

    if (tid < 128) biass[tid] = bias[col0 + tid];

    auto issue = [&](int kt, int b) {
        uint32_t abase = sb + b * STAGE;
        uint32_t bbase = abase + 8192;
        const __half* A = ap[(kt >> 2) & 3];
        int kb = (kt & 3) * 64;
        #pragma unroll
        for (int t = 0; t < 2; t++) {   // A: 64 rows x 8 chunks of 16B
            int i = tid + t * 256;
            int m = i >> 3, c = i & 7;
            int gr = row0 + m;
            uint32_t dst = abase + m * 128 + ((c ^ (m & 7)) << 4);
            const __half* src = A + (size_t)min(gr, N_NODES - 1) * 256 + kb + c * 8;
            uint32_t sz = (gr < N_NODES) ? 16u : 0u;
            asm volatile("cp.async.cg.shared.global [%0], [%1], 16, %2;"
                :: "r"(dst), "l"(src), "r"(sz));
        }
        #pragma unroll
        for (int t = 0; t < 4; t++) {   // B: 64 rows x 16 chunks
            int i = tid + t * 256;
            int k = i >> 4, c = i & 15;
            uint32_t cp = (uint32_t)((c & 8) | ((c ^ (k & 7)) & 7));
            uint32_t dst = bbase + k * 256 + (cp << 4);
            const __half* src = Bw + (size_t)(kt * 64 + k) * Nw + col0 + c * 8;
            asm volatile("cp.async.cg.shared.global [%0], [%1], 16;"
                :: "r"(dst), "l"(src));
        }
        CP_COMMIT();
    };

    int wr = wid >> 2, wc = wid & 3;    // warp grid 2x4; warp tile 32x32
    float acc[2][4][4];
    #pragma unroll
    for (int mt = 0; mt < 2; mt++)
        #pragma unroll
        for (int nt = 0; nt < 4; nt++)
            #pragma unroll
            for (int i = 0; i < 4; i++) acc[mt][nt][i] = 0.f;

    issue(0, 0);
    issue(1, 1);
    issue(2, 2);

    for (int kt = 0; kt < NKT; kt++) {
        int b = kt % 3;
        if (kt + 3 <= NKT)      asm volatile("cp.async.wait_group 2;" ::: "memory");
        else if (kt + 2 == NKT) asm volatile("cp.async.wait_group 1;" ::: "memory");
        else                    asm volatile("cp.async.wait_group 0;" ::: "memory");
        __syncthreads();
        uint32_t abase = sb + b * STAGE;
        uint32_t bbase = abase + 8192;
        #pragma unroll
        for (int ks = 0; ks < 4; ks++) {
            uint32_t af[2][4];
            #pragma unroll
            for (int mt = 0; mt < 2; mt++) {
                int m = wr * 32 + mt * 16 + (lane & 15);
                int c = ks * 2 + (lane >> 4);
                ldm_x4(af[mt], abase + m * 128 + ((c ^ (m & 7)) << 4));
            }
            uint32_t bf[2][4];
            #pragma unroll
            for (int nt2 = 0; nt2 < 2; nt2++) {
                int k = ks * 16 + (lane & 15);
                int c = ((wc * 32 + nt2 * 16) >> 3) + (lane >> 4);
                uint32_t cp = (uint32_t)((c & 8) | ((c ^ (k & 7)) & 7));
                ldm_x4_t(bf[nt2], bbase + k * 256 + (cp << 4));
            }
            #pragma unroll
            for (int mt = 0; mt < 2; mt++)
                #pragma unroll
                for (int nt2 = 0; nt2 < 2; nt2++) {
                    mma_f16(acc[mt][nt2 * 2],     af[mt], bf[nt2][0], bf[nt2][1]);
                    mma_f16(acc[mt][nt2 * 2 + 1], af[mt], bf[nt2][2], bf[nt2][3]);
                }
        }
        __syncthreads();
        if (kt + 3 < NKT) issue(kt + 3, b);
    }

    // epilogue
    int g = lane >> 2, tg = lane & 3;
    #pragma unroll
    for (int mt = 0; mt < 2; mt++) {
        #pragma unroll
        for (int hf = 0; hf < 2; hf++) {
            int gr = row0 + wr * 32 + mt * 16 + g + hf * 8;
            if (gr >= N_NODES) continue;
            #pragma unroll
            for (int nt = 0; nt < 4; nt++) {
                int lc = wc * 32 + nt * 8 + tg * 2;
                int gc = col0 + lc;
                float v0 = acc[mt][nt][hf * 2 + 0] + biass[lc];
                float v1 = acc[mt][nt][hf * 2 + 1] + biass[lc + 1];
                if (MODE == 0) {
                    float s0 = 1.f / (1.f + __expf(-v0));
                    float s1 = 1.f / (1.f + __expf(-v1));
                    if (gc < 256) {
                        *(__half2*)(Zh + (size_t)gr * 256 + gc) = __floats2half2_rn(s0, s1);
                    } else {
                        int cc = gc - 256;
                        float h0v = hfull[(size_t)gr * 256 + cc];
                        float h1v = hfull[(size_t)gr * 256 + cc + 1];
                        *(__half2*)(auxh + (size_t)gr * 256 + cc) =
                            __floats2half2_rn(h0v * s0, h1v * s1);
                    }
                } else if (MODE == 1) {
                    float t0 = 1.f - 2.f / (__expf(2.f * v0) + 1.f);
                    float t1 = 1.f - 2.f / (__expf(2.f * v1) + 1.f);
                    float2 z = __half22float2(*(const __half2*)(Zh + (size_t)gr * 256 + gc));
                    float h0v = hfull[(size_t)gr * 256 + gc];
                    float h1v = hfull[(size_t)gr * 256 + gc + 1];
                    float o0 = z.x * h0v + (1.f - z.x) * t0;
                    float o1 = z.y * h1v + (1.f - z.y) * t1;
                    *(float2*)(C + (size_t)gr * 256 + gc) = make_float2(o0, o1);
                    *(__half2*)(auxh + (size_t)gr * 256 + gc) =
                        __floats2half2_rn(fmaxf(o0, 0.f), fmaxf(o1, 0.f));
                } else {
                    *(float2*)(C + (size_t)gr * 128 + gc) = make_float2(v0, v1);
                }
            }
        }
    }
}

// ---------------- launch ----------------
extern "C" void kernel_launch(void* const* d_in, const int* in_sizes, int n_in,
                              void* d_out, int out_size) {
    const float* x   = (const float*)d_in[0];
    const float* h   = (const float*)d_in[1];
    const int*   ei  = (const int*)d_in[2];
    const float* w   = (const float*)d_in[3];
    const float* Wxz = (const float*)d_in[4];  const float* bxz = (const float*)d_in[5];
    const float* Whz = (const float*)d_in[6];  const float* bhz = (const float*)d_in[7];
    const float* Wxr = (const float*)d_in[8];  const float* bxr = (const float*)d_in[9];
    const float* Whr = (const float*)d_in[10]; const float* bhr = (const float*)d_in[11];
    const float* Wxh = (const float*)d_in[12]; const float* bxh = (const float*)d_in[13];
    const float* Whh = (const float*)d_in[14]; const float* bhh = (const float*)d_in[15];
    const float* Wl  = (const float*)d_in[16]; const float* bl  = (const float*)d_in[17];

    float* out = (float*)d_out;                   // [N,128]
    float* h0  = out + (size_t)N_NODES * 128;     // [N,256]

    __half *p_xh, *p_hh, *p_Lxh, *p_Lhh, *p_hrh, *p_Lhrh, *p_h0rh, *p_Zh;
    __half *p_Wzrh, *p_WhPh, *p_Wlth;
    float *p_bzr, *p_bh;
    cudaGetSymbolAddress((void**)&p_xh,   g_xh);
    cudaGetSymbolAddress((void**)&p_hh,   g_hh);
    cudaGetSymbolAddress((void**)&p_Lxh,  g_Lxh);
    cudaGetSymbolAddress((void**)&p_Lhh,  g_Lhh);
    cudaGetSymbolAddress((void**)&p_hrh,  g_hrh);
    cudaGetSymbolAddress((void**)&p_Lhrh, g_Lhrh);
    cudaGetSymbolAddress((void**)&p_h0rh, g_h0rh);
    cudaGetSymbolAddress((void**)&p_Zh,   g_Zh);
    cudaGetSymbolAddress((void**)&p_Wzrh, g_Wzrh);
    cudaGetSymbolAddress((void**)&p_WhPh, g_WhPh);
    cudaGetSymbolAddress((void**)&p_Wlth, g_Wlth);
    cudaGetSymbolAddress((void**)&p_bzr,  g_bzr);
    cudaGetSymbolAddress((void**)&p_bh,   g_bh);

    const int SMEM_TOT = 3 * 24576 + 512;   // 74240
    cudaFuncSetAttribute(gemmh<1024, 0>, cudaFuncAttributeMaxDynamicSharedMemorySize, SMEM_TOT);
    cudaFuncSetAttribute(gemmh<1024, 1>, cudaFuncAttributeMaxDynamicSharedMemorySize, SMEM_TOT);
    cudaFuncSetAttribute(gemmh<256, 2>,  cudaFuncAttributeMaxDynamicSharedMemorySize, SMEM_TOT);
    cudaFuncSetAttribute(scan_kernel, cudaFuncAttributeMaxDynamicSharedMemorySize, 80000);

    // graph normalization + CSR build
    zero_kernel<<<(N_NODES + 255) / 256, 256>>>();
    deg_hist_kernel<<<(N_EDGES + 255) / 256, 256>>>(ei, w);
    scan_kernel<<<1, 1024, 80000>>>();
    scatter_kernel<<<(N_EDGES + 255) / 256, 256>>>(ei, w);

    // fused cvt + weight/bias packing
    setup_all<<<(N_NODES * 256 + 255) / 256, 256>>>(
        x, h, Wxz, Whz, Wxr, Whr, Wxh, Whh, Wl, bxz, bhz, bxr, bhr, bxh, bhh);

    // fused SpMM: Lx and Lh in one pass (warp per row)
    spmmw<true><<<(N_NODES + 7) / 8, 256>>>(
        (const __half2*)p_xh, (const __half2*)p_hh,
        (__half2*)p_Lxh, (__half2*)p_Lhh);

    int gy = (N_NODES + 63) / 64;    // 313

    // GEMM1: [x|Lx|h|Lh] @ Wzr -> Zh (half) + hr=h*R (half)
    {
        dim3 grid(4, gy);
        gemmh<1024, 0><<<grid, 256, SMEM_TOT>>>(
            p_xh, p_Lxh, p_hh, p_Lhh, p_Wzrh, 512, p_bzr, nullptr, h, p_Zh, p_hrh);
    }

    // L(hr)
    spmmw<false><<<(N_NODES + 7) / 8, 256>>>(
        (const __half2*)p_hrh, nullptr, (__half2*)p_Lhrh, nullptr);

    // GEMM2: h0 = Z*h + (1-Z)*tanh([x|Lx|hr|Lhr] @ WhP + bh); relu(h0) -> half
    {
        dim3 grid(2, gy);
        gemmh<1024, 1><<<grid, 256, SMEM_TOT>>>(
            p_xh, p_Lxh, p_hrh, p_Lhrh, p_WhPh, 256, p_bh, h0, h, p_Zh, p_h0rh);
    }

    // GEMM3: out = relu(h0) @ Wl + bl
    {
        dim3 grid(1, gy);
        gemmh<256, 2><<<grid, 256, SMEM_TOT>>>(
            p_h0rh, p_h0rh, p_h0rh, p_h0rh, p_Wlth, 128, bl, out, nullptr, nullptr, nullptr);
    }
}

// round 7
// speedup vs baseline: 4.4230x; 1.0240x over previous
#include <cuda_runtime.h>
#include <cuda_fp16.h>
#include <math.h>
#include <stdint.h>

#define N_NODES 20000
#define N_EDGES 320000

// ---------------- PTX helpers ----------------
__device__ __forceinline__ uint32_t smem_u32(const void* p) {
    uint32_t a;
    asm("{ .reg .u64 t; cvta.to.shared.u64 t, %1; cvt.u32.u64 %0, t; }" : "=r"(a) : "l"(p));
    return a;
}
__device__ __forceinline__ void ldm_x4(uint32_t r[4], uint32_t addr) {
    asm volatile("ldmatrix.sync.aligned.m8n8.x4.shared.b16 {%0,%1,%2,%3}, [%4];"
        : "=r"(r[0]), "=r"(r[1]), "=r"(r[2]), "=r"(r[3]) : "r"(addr));
}
__device__ __forceinline__ void ldm_x4_t(uint32_t r[4], uint32_t addr) {
    asm volatile("ldmatrix.sync.aligned.m8n8.x4.trans.shared.b16 {%0,%1,%2,%3}, [%4];"
        : "=r"(r[0]), "=r"(r[1]), "=r"(r[2]), "=r"(r[3]) : "r"(addr));
}
__device__ __forceinline__ void mma_f16(float* c, const uint32_t a[4], uint32_t b0, uint32_t b1) {
    asm volatile(
        "mma.sync.aligned.m16n8k16.row.col.f32.f16.f16.f32 "
        "{%0,%1,%2,%3},{%4,%5,%6,%7},{%8,%9},{%0,%1,%2,%3};"
        : "+f"(c[0]), "+f"(c[1]), "+f"(c[2]), "+f"(c[3])
        : "r"(a[0]), "r"(a[1]), "r"(a[2]), "r"(a[3]), "r"(b0), "r"(b1));
}
#define CP_COMMIT() asm volatile("cp.async.commit_group;" ::: "memory")

// ---------------- scratch ----------------
__device__ float g_deg[N_NODES];
__device__ float g_dis[N_NODES];
__device__ int   g_cnt[N_NODES];
__device__ int   g_cur[N_NODES];
__device__ int   g_rowptr[N_NODES + 1];
__device__ int   g_srcs[N_EDGES];
__device__ float g_vals[N_EDGES];

__device__ __align__(16) __half g_xh  [(size_t)N_NODES * 256];
__device__ __align__(16) __half g_hh  [(size_t)N_NODES * 256];
__device__ __align__(16) __half g_Lxh [(size_t)N_NODES * 256];
__device__ __align__(16) __half g_Lhh [(size_t)N_NODES * 256];
__device__ __align__(16) __half g_hrh [(size_t)N_NODES * 256];
__device__ __align__(16) __half g_Lhrh[(size_t)N_NODES * 256];
__device__ __align__(16) __half g_h0rh[(size_t)N_NODES * 256];
__device__ __align__(16) __half g_Zh  [(size_t)N_NODES * 256];

__device__ __align__(16) __half g_Wzrh[1024 * 512];   // [K=1024][N=512]
__device__ __align__(16) __half g_WhPh[1024 * 256];   // [K=1024][N=256]
__device__ __align__(16) __half g_Wlth[256 * 128];    // [K=256][N=128]
__device__ float g_bzr[512];
__device__ float g_bh[256];

// ---------------- setup kernels ----------------
__global__ void zero_kernel() {
    int i = blockIdx.x * blockDim.x + threadIdx.x;
    if (i < N_NODES) { g_deg[i] = 0.f; g_cnt[i] = 0; g_cur[i] = 0; }
}

// fused: edge histogram (blocks 0..1249) + cvt/pack setup (blocks 1250..)
#define EDGE_BLOCKS 1250
__global__ void deg_setup(const int* __restrict__ ei, const float* __restrict__ w,
                          const float* __restrict__ x, const float* __restrict__ h,
                          const float* __restrict__ Wxz, const float* __restrict__ Whz,
                          const float* __restrict__ Wxr, const float* __restrict__ Whr,
                          const float* __restrict__ Wxh, const float* __restrict__ Whh,
                          const float* __restrict__ Wl,
                          const float* __restrict__ bxz, const float* __restrict__ bhz,
                          const float* __restrict__ bxr, const float* __restrict__ bhr,
                          const float* __restrict__ bxh, const float* __restrict__ bhh) {
    int b = blockIdx.x;
    if (b < EDGE_BLOCKS) {
        int e = b * 256 + threadIdx.x;
        if (e < N_EDGES) {
            atomicAdd(&g_deg[ei[e]], w[e]);
            atomicAdd(&g_cnt[ei[N_EDGES + e]], 1);
        }
        return;
    }
    int i = (b - EDGE_BLOCKS) * 256 + threadIdx.x;
    if (i < N_NODES * 256) {
        g_xh[i] = __float2half_rn(x[i]);
        g_hh[i] = __float2half_rn(h[i]);
    }
    if (i < 1024 * 512) {
        int k = i >> 9, j = i & 511;
        int jj = j & 255;
        const float* Wx = (j < 256) ? Wxz : Wxr;
        const float* Wh = (j < 256) ? Whz : Whr;
        float v;
        if (k < 512) v = Wx[((k >= 256) ? 65536 : 0) + (k & 255) * 256 + jj];
        else         v = Wh[((k >= 768) ? 65536 : 0) + (k & 255) * 256 + jj];
        g_Wzrh[i] = __float2half_rn(v);
        if (i < 1024 * 256) {
            int k2 = i >> 8, jj2 = i & 255;
            float v2;
            if (k2 < 512) v2 = Wxh[((k2 >= 256) ? 65536 : 0) + (k2 & 255) * 256 + jj2];
            else          v2 = Whh[((k2 >= 768) ? 65536 : 0) + (k2 & 255) * 256 + jj2];
            g_WhPh[i] = __float2half_rn(v2);
        }
        if (i < 256 * 128) g_Wlth[i] = __float2half_rn(Wl[i]);
        if (i < 512) {
            if (i < 256) { g_bzr[i] = bxz[i] + bhz[i]; g_bh[i] = bxh[i] + bhh[i]; }
            else          g_bzr[i] = bxr[i - 256] + bhr[i - 256];
        }
    }
}

// scan (coalesced smem staging) + dis computation fused
__global__ void scan_kernel() {
    extern __shared__ int sh[];
    __shared__ int warp_sums[32];
    const int PER = 20;
    int tid = threadIdx.x;
    for (int i = tid; i < N_NODES; i += 1024) {
        float dg = g_deg[i];
        g_dis[i] = (dg > 0.f) ? rsqrtf(dg) : 0.f;
    }
    for (int i = tid; i < N_NODES; i += 1024) sh[i] = g_cnt[i];
    __syncthreads();
    int base = tid * PER;
    int loc[PER];
    int s = 0;
    #pragma unroll
    for (int i = 0; i < PER; i++) {
        int idx = base + i;
        int v = (idx < N_NODES) ? sh[idx] : 0;
        loc[i] = s; s += v;
    }
    int lane = tid & 31, wid = tid >> 5;
    int v = s;
    #pragma unroll
    for (int o = 1; o < 32; o <<= 1) {
        int t = __shfl_up_sync(0xFFFFFFFFu, v, o);
        if (lane >= o) v += t;
    }
    if (lane == 31) warp_sums[wid] = v;
    __syncthreads();
    if (wid == 0) {
        int wv = warp_sums[lane];
        #pragma unroll
        for (int o = 1; o < 32; o <<= 1) {
            int t = __shfl_up_sync(0xFFFFFFFFu, wv, o);
            if (lane >= o) wv += t;
        }
        warp_sums[lane] = wv;
    }
    __syncthreads();
    int ex = v - s + (wid ? warp_sums[wid - 1] : 0);
    #pragma unroll
    for (int i = 0; i < PER; i++) {
        int idx = base + i;
        if (idx < N_NODES) g_rowptr[idx] = ex + loc[i];
    }
    if (tid == 1023) g_rowptr[N_NODES] = ex + s;
}

__global__ void scatter_kernel(const int* __restrict__ ei, const float* __restrict__ w) {
    int e = blockIdx.x * blockDim.x + threadIdx.x;
    if (e < N_EDGES) {
        int s = ei[e];
        int d = ei[N_EDGES + e];
        int pos = g_rowptr[d] + atomicAdd(&g_cur[d], 1);
        g_srcs[pos] = s;
        g_vals[pos] = -g_dis[s] * w[e] * g_dis[d];
    }
}

// ---------------- SpMM: warp-per-row, uint4 gathers (LDG.128), shuffle-broadcast --------
template <bool TWO>
__global__ void __launch_bounds__(256) spmmw(
    const uint4* __restrict__ X, const uint4* __restrict__ H,
    uint4* __restrict__ OX, uint4* __restrict__ OH)
{
    int wid = threadIdx.x >> 5, lane = threadIdx.x & 31;
    int d = blockIdx.x * 8 + wid;
    if (d >= N_NODES) return;
    int s0 = g_rowptr[d], s1 = g_rowptr[d + 1];
    float ax[8] = {0.f, 0.f, 0.f, 0.f, 0.f, 0.f, 0.f, 0.f};
    float ah[8] = {0.f, 0.f, 0.f, 0.f, 0.f, 0.f, 0.f, 0.f};
    for (int base = s0; base < s1; base += 32) {
        int n = min(32, s1 - base);
        int idx = 0; float val = 0.f;
        if (lane < n) { idx = g_srcs[base + lane] * 32; val = g_vals[base + lane]; }
        for (int j = 0; j < n; j++) {
            int so  = __shfl_sync(0xFFFFFFFFu, idx, j);
            float v = __shfl_sync(0xFFFFFFFFu, val, j);
            uint4 px = X[so + lane];
            const __half2* hx = (const __half2*)&px;
            #pragma unroll
            for (int k = 0; k < 4; k++) {
                float2 f = __half22float2(hx[k]);
                ax[2 * k]     = fmaf(v, f.x, ax[2 * k]);
                ax[2 * k + 1] = fmaf(v, f.y, ax[2 * k + 1]);
            }
            if (TWO) {
                uint4 ph = H[so + lane];
                const __half2* hh2 = (const __half2*)&ph;
                #pragma unroll
                for (int k = 0; k < 4; k++) {
                    float2 f = __half22float2(hh2[k]);
                    ah[2 * k]     = fmaf(v, f.x, ah[2 * k]);
                    ah[2 * k + 1] = fmaf(v, f.y, ah[2 * k + 1]);
                }
            }
        }
    }
    uint4 o;
    __half2* ho = (__half2*)&o;
    #pragma unroll
    for (int k = 0; k < 4; k++) ho[k] = __floats2half2_rn(ax[2 * k], ax[2 * k + 1]);
    OX[d * 32 + lane] = o;
    if (TWO) {
        uint4 o2;
        __half2* ho2 = (__half2*)&o2;
        #pragma unroll
        for (int k = 0; k < 4; k++) ho2[k] = __floats2half2_rn(ah[2 * k], ah[2 * k + 1]);
        OH[d * 32 + lane] = o2;
    }
}

// ---------------- fp16 tensor-core GEMM, BM=64 BN=128 BK=64, 3-stage, 3 CTA/SM ----------
// 8 warps (2x4), warp tile 32x32, mma m16n8k16.
// MODE 0: Z=sigmoid -> Zh (cols<256); R=sigmoid, hr=hfull*R -> auxh (cols>=256)
// MODE 1: h0 = z*hfull + (1-z)*tanh(v) -> C(fp32,ldc256); relu(h0) -> auxh
// MODE 2: v + bias -> C (fp32, ldc=128)
template <int KTOT, int MODE>
__global__ void __launch_bounds__(256, 3) gemmh(
    const __half* __restrict__ a0, const __half* __restrict__ a1,
    const __half* __restrict__ a2, const __half* __restrict__ a3,
    const __half* __restrict__ Bw, int Nw,
    const float* __restrict__ bias,
    float* __restrict__ C,
    const float* __restrict__ hfull,
    __half* __restrict__ Zh,
    __half* __restrict__ auxh)
{
    constexpr int NKT = KTOT / 64;
    constexpr int STAGE = 24576;        // A 8KB + B 16KB
    extern __shared__ char smem[];
    uint32_t sb = smem_u32(smem);
    float* biass = (float*)(smem + 3 * STAGE);
    int tid = threadIdx.x, wid = tid >> 5, lane = tid & 31;
    int row0 = blockIdx.y * 64;
    int col0 = blockIdx.x * 128;
    const __half* ap[4] = {a0, a1, a2, a3};

    if (tid < 128) biass[tid] = bias[col0 + tid];

    auto issue = [&](int kt, int b) {
        uint32_t abase = sb + b * STAGE;
        uint32_t bbase = abase + 8192;
        const __half* A = ap[(kt >> 2) & 3];
        int kb = (kt & 3) * 64;
        #pragma unroll
        for (int t = 0; t < 2; t++) {   // A: 64 rows x 8 chunks of 16B
            int i = tid + t * 256;
            int m = i >> 3, c = i & 7;
            int gr = row0 + m;
            uint32_t dst = abase + m * 128 + ((c ^ (m & 7)) << 4);
            const __half* src = A + (size_t)min(gr, N_NODES - 1) * 256 + kb + c * 8;
            uint32_t sz = (gr < N_NODES) ? 16u : 0u;
            asm volatile("cp.async.cg.shared.global [%0], [%1], 16, %2;"
                :: "r"(dst), "l"(src), "r"(sz));
        }
        #pragma unroll
        for (int t = 0; t < 4; t++) {   // B: 64 rows x 16 chunks
            int i = tid + t * 256;
            int k = i >> 4, c = i & 15;
            uint32_t cp = (uint32_t)((c & 8) | ((c ^ (k & 7)) & 7));
            uint32_t dst = bbase + k * 256 + (cp << 4);
            const __half* src = Bw + (size_t)(kt * 64 + k) * Nw + col0 + c * 8;
            asm volatile("cp.async.cg.shared.global [%0], [%1], 16;"
                :: "r"(dst), "l"(src));
        }
        CP_COMMIT();
    };

    int wr = wid >> 2, wc = wid & 3;    // warp grid 2x4; warp tile 32x32
    float acc[2][4][4];
    #pragma unroll
    for (int mt = 0; mt < 2; mt++)
        #pragma unroll
        for (int nt = 0; nt < 4; nt++)
            #pragma unroll
            for (int i = 0; i < 4; i++) acc[mt][nt][i] = 0.f;

    issue(0, 0);
    issue(1, 1);
    issue(2, 2);

    for (int kt = 0; kt < NKT; kt++) {
        int b = kt % 3;
        if (kt + 3 <= NKT)      asm volatile("cp.async.wait_group 2;" ::: "memory");
        else if (kt + 2 == NKT) asm volatile("cp.async.wait_group 1;" ::: "memory");
        else                    asm volatile("cp.async.wait_group 0;" ::: "memory");
        __syncthreads();
        uint32_t abase = sb + b * STAGE;
        uint32_t bbase = abase + 8192;
        #pragma unroll
        for (int ks = 0; ks < 4; ks++) {
            uint32_t af[2][4];
            #pragma unroll
            for (int mt = 0; mt < 2; mt++) {
                int m = wr * 32 + mt * 16 + (lane & 15);
                int c = ks * 2 + (lane >> 4);
                ldm_x4(af[mt], abase + m * 128 + ((c ^ (m & 7)) << 4));
            }
            uint32_t bf[2][4];
            #pragma unroll
            for (int nt2 = 0; nt2 < 2; nt2++) {
                int k = ks * 16 + (lane & 15);
                int c = ((wc * 32 + nt2 * 16) >> 3) + (lane >> 4);
                uint32_t cp = (uint32_t)((c & 8) | ((c ^ (k & 7)) & 7));
                ldm_x4_t(bf[nt2], bbase + k * 256 + (cp << 4));
            }
            #pragma unroll
            for (int mt = 0; mt < 2; mt++)
                #pragma unroll
                for (int nt2 = 0; nt2 < 2; nt2++) {
                    mma_f16(acc[mt][nt2 * 2],     af[mt], bf[nt2][0], bf[nt2][1]);
                    mma_f16(acc[mt][nt2 * 2 + 1], af[mt], bf[nt2][2], bf[nt2][3]);
                }
        }
        __syncthreads();
        if (kt + 3 < NKT) issue(kt + 3, b);
    }

    // epilogue
    int g = lane >> 2, tg = lane & 3;
    #pragma unroll
    for (int mt = 0; mt < 2; mt++) {
        #pragma unroll
        for (int hf = 0; hf < 2; hf++) {
            int gr = row0 + wr * 32 + mt * 16 + g + hf * 8;
            if (gr >= N_NODES) continue;
            #pragma unroll
            for (int nt = 0; nt < 4; nt++) {
                int lc = wc * 32 + nt * 8 + tg * 2;
                int gc = col0 + lc;
                float v0 = acc[mt][nt][hf * 2 + 0] + biass[lc];
                float v1 = acc[mt][nt][hf * 2 + 1] + biass[lc + 1];
                if (MODE == 0) {
                    float s0 = 1.f / (1.f + __expf(-v0));
                    float s1 = 1.f / (1.f + __expf(-v1));
                    if (gc < 256) {
                        *(__half2*)(Zh + (size_t)gr * 256 + gc) = __floats2half2_rn(s0, s1);
                    } else {
                        int cc = gc - 256;
                        float h0v = hfull[(size_t)gr * 256 + cc];
                        float h1v = hfull[(size_t)gr * 256 + cc + 1];
                        *(__half2*)(auxh + (size_t)gr * 256 + cc) =
                            __floats2half2_rn(h0v * s0, h1v * s1);
                    }
                } else if (MODE == 1) {
                    float t0 = 1.f - 2.f / (__expf(2.f * v0) + 1.f);
                    float t1 = 1.f - 2.f / (__expf(2.f * v1) + 1.f);
                    float2 z = __half22float2(*(const __half2*)(Zh + (size_t)gr * 256 + gc));
                    float h0v = hfull[(size_t)gr * 256 + gc];
                    float h1v = hfull[(size_t)gr * 256 + gc + 1];
                    float o0 = z.x * h0v + (1.f - z.x) * t0;
                    float o1 = z.y * h1v + (1.f - z.y) * t1;
                    *(float2*)(C + (size_t)gr * 256 + gc) = make_float2(o0, o1);
                    *(__half2*)(auxh + (size_t)gr * 256 + gc) =
                        __floats2half2_rn(fmaxf(o0, 0.f), fmaxf(o1, 0.f));
                } else {
                    *(float2*)(C + (size_t)gr * 128 + gc) = make_float2(v0, v1);
                }
            }
        }
    }
}

// ---------------- launch ----------------
extern "C" void kernel_launch(void* const* d_in, const int* in_sizes, int n_in,
                              void* d_out, int out_size) {
    const float* x   = (const float*)d_in[0];
    const float* h   = (const float*)d_in[1];
    const int*   ei  = (const int*)d_in[2];
    const float* w   = (const float*)d_in[3];
    const float* Wxz = (const float*)d_in[4];  const float* bxz = (const float*)d_in[5];
    const float* Whz = (const float*)d_in[6];  const float* bhz = (const float*)d_in[7];
    const float* Wxr = (const float*)d_in[8];  const float* bxr = (const float*)d_in[9];
    const float* Whr = (const float*)d_in[10]; const float* bhr = (const float*)d_in[11];
    const float* Wxh = (const float*)d_in[12]; const float* bxh = (const float*)d_in[13];
    const float* Whh = (const float*)d_in[14]; const float* bhh = (const float*)d_in[15];
    const float* Wl  = (const float*)d_in[16]; const float* bl  = (const float*)d_in[17];

    float* out = (float*)d_out;                   // [N,128]
    float* h0  = out + (size_t)N_NODES * 128;     // [N,256]

    __half *p_xh, *p_hh, *p_Lxh, *p_Lhh, *p_hrh, *p_Lhrh, *p_h0rh, *p_Zh;
    __half *p_Wzrh, *p_WhPh, *p_Wlth;
    float *p_bzr, *p_bh;
    cudaGetSymbolAddress((void**)&p_xh,   g_xh);
    cudaGetSymbolAddress((void**)&p_hh,   g_hh);
    cudaGetSymbolAddress((void**)&p_Lxh,  g_Lxh);
    cudaGetSymbolAddress((void**)&p_Lhh,  g_Lhh);
    cudaGetSymbolAddress((void**)&p_hrh,  g_hrh);
    cudaGetSymbolAddress((void**)&p_Lhrh, g_Lhrh);
    cudaGetSymbolAddress((void**)&p_h0rh, g_h0rh);
    cudaGetSymbolAddress((void**)&p_Zh,   g_Zh);
    cudaGetSymbolAddress((void**)&p_Wzrh, g_Wzrh);
    cudaGetSymbolAddress((void**)&p_WhPh, g_WhPh);
    cudaGetSymbolAddress((void**)&p_Wlth, g_Wlth);
    cudaGetSymbolAddress((void**)&p_bzr,  g_bzr);
    cudaGetSymbolAddress((void**)&p_bh,   g_bh);

    const int SMEM_TOT = 3 * 24576 + 512;   // 74240
    cudaFuncSetAttribute(gemmh<1024, 0>, cudaFuncAttributeMaxDynamicSharedMemorySize, SMEM_TOT);
    cudaFuncSetAttribute(gemmh<1024, 1>, cudaFuncAttributeMaxDynamicSharedMemorySize, SMEM_TOT);
    cudaFuncSetAttribute(gemmh<256, 2>,  cudaFuncAttributeMaxDynamicSharedMemorySize, SMEM_TOT);
    cudaFuncSetAttribute(scan_kernel, cudaFuncAttributeMaxDynamicSharedMemorySize, 80000);

    // graph normalization + CSR build; setup fused into the histogram launch
    zero_kernel<<<(N_NODES + 255) / 256, 256>>>();
    deg_setup<<<EDGE_BLOCKS + (N_NODES * 256 + 255) / 256, 256>>>(
        ei, w, x, h, Wxz, Whz, Wxr, Whr, Wxh, Whh, Wl,
        bxz, bhz, bxr, bhr, bxh, bhh);
    scan_kernel<<<1, 1024, 80000>>>();
    scatter_kernel<<<(N_EDGES + 255) / 256, 256>>>(ei, w);

    // fused SpMM: Lx and Lh in one pass (warp per row, uint4 gathers)
    spmmw<true><<<(N_NODES + 7) / 8, 256>>>(
        (const uint4*)p_xh, (const uint4*)p_hh,
        (uint4*)p_Lxh, (uint4*)p_Lhh);

    int gy = (N_NODES + 63) / 64;    // 313

    // GEMM1: [x|Lx|h|Lh] @ Wzr -> Zh (half) + hr=h*R (half)
    {
        dim3 grid(4, gy);
        gemmh<1024, 0><<<grid, 256, SMEM_TOT>>>(
            p_xh, p_Lxh, p_hh, p_Lhh, p_Wzrh, 512, p_bzr, nullptr, h, p_Zh, p_hrh);
    }

    // L(hr)
    spmmw<false><<<(N_NODES + 7) / 8, 256>>>(
        (const uint4*)p_hrh, nullptr, (uint4*)p_Lhrh, nullptr);

    // GEMM2: h0 = Z*h + (1-Z)*tanh([x|Lx|hr|Lhr] @ WhP + bh); relu(h0) -> half
    {
        dim3 grid(2, gy);
        gemmh<1024, 1><<<grid, 256, SMEM_TOT>>>(
            p_xh, p_Lxh, p_hrh, p_Lhrh, p_WhPh, 256, p_bh, h0, h, p_Zh, p_h0rh);
    }

    // GEMM3: out = relu(h0) @ Wl + bl
    {
        dim3 grid(1, gy);
        gemmh<256, 2><<<grid, 256, SMEM_TOT>>>(
            p_h0rh, p_h0rh, p_h0rh, p_h0rh, p_Wlth, 128, bl, out, nullptr, nullptr, nullptr);
    }
}